// round 14
// baseline (speedup 1.0000x reference)
#include <cuda_runtime.h>
#include <cuda_bf16.h>
#include <cuda_fp16.h>
#include <math.h>
#include <stdint.h>

#define NROWS 131072
#define E_DIM 1024
#define L_DIM 512
#define D_DIM 256
#define NI    50

// ---------------- device scratch (allocation-free rule) ----------------
__device__ __half g_h16[(size_t)NROWS * L_DIM];   // h as single fp16
__device__ __half g_wc16[L_DIM * E_DIM];          // Wc single fp16
__device__ __half g_wthi[2 * D_DIM * L_DIM];      // Wcat fp16 hi/lo
__device__ __half g_wtlo[2 * D_DIM * L_DIM];
__device__ float g_bcat[2 * D_DIM];
__device__ float g_A[(size_t)NROWS * 2];
__device__ int      g_hist[16384];
__device__ unsigned g_maxkey[2];
__device__ float    g_Z[2];
__device__ float    g_bag[2 * L_DIM];
__device__ int      g_binhi, g_binlo;
__device__ int      g_nhi, g_nlo;
__device__ float g_chv[NROWS]; __device__ int g_chi[NROWS];
__device__ float g_clv[NROWS]; __device__ int g_cli[NROWS];
__device__ int   g_inst[2 * NI];

// ---------------- PTX helpers ----------------
__device__ __forceinline__ uint32_t smem_u32(const void* p) {
    uint32_t a;
    asm("{ .reg .u64 t; cvta.to.shared.u64 t, %1; cvt.u32.u64 %0, t; }" : "=r"(a) : "l"(p));
    return a;
}
__device__ __forceinline__ void cp16(uint32_t s, const void* g) {
    asm volatile("cp.async.cg.shared.global [%0], [%1], 16;" :: "r"(s), "l"(g));
}
__device__ __forceinline__ void ldsm4(uint32_t* r, uint32_t addr) {
    asm volatile("ldmatrix.sync.aligned.m8n8.x4.shared.b16 {%0,%1,%2,%3}, [%4];"
                 : "=r"(r[0]), "=r"(r[1]), "=r"(r[2]), "=r"(r[3]) : "r"(addr));
}
__device__ __forceinline__ void mma16816h(float* c, const uint32_t* a, const uint32_t* b) {
    asm volatile(
        "mma.sync.aligned.m16n8k16.row.col.f32.f16.f16.f32 "
        "{%0,%1,%2,%3}, {%4,%5,%6,%7}, {%8,%9}, {%0,%1,%2,%3};"
        : "+f"(c[0]), "+f"(c[1]), "+f"(c[2]), "+f"(c[3])
        : "r"(a[0]), "r"(a[1]), "r"(a[2]), "r"(a[3]), "r"(b[0]), "r"(b[1]));
}

// monotone float <-> uint key
__device__ __forceinline__ unsigned monoKey(float f) {
    unsigned u = __float_as_uint(f);
    return (u & 0x80000000u) ? ~u : (u | 0x80000000u);
}
__device__ __forceinline__ float monoDecode(unsigned k) {
    unsigned u = (k & 0x80000000u) ? (k & 0x7FFFFFFFu) : ~k;
    return __uint_as_float(u);
}

__device__ __forceinline__ uint32_t packh2(float a, float b) {
    __half2 t = __halves2half2(__float2half(a), __float2half(b));
    return *(uint32_t*)&t;
}

// ---------------- init ----------------
__global__ void init_kernel() {
    int i = blockIdx.x * blockDim.x + threadIdx.x;
    if (i < 2 * NROWS) g_A[i] = 0.f;
    if (i < 16384) g_hist[i] = 0;
    if (i < 2 * L_DIM) g_bag[i] = 0.f;
    if (i < 2) { g_Z[i] = 0.f; g_maxkey[i] = 0u; }
    if (i == 0) { g_nhi = 0; g_nlo = 0; }
}

// ---------------- fp32 -> fp16 convert (Wc single) ----------------
__global__ void cvtw_kernel(const float4* __restrict__ in, __half2* __restrict__ out16, int n4) {
    int i = blockIdx.x * blockDim.x + threadIdx.x;
    int stride = gridDim.x * blockDim.x;
    for (; i < n4; i += stride) {
        float4 v = in[i];
        out16[2 * i]     = __halves2half2(__float2half(v.x), __float2half(v.y));
        out16[2 * i + 1] = __halves2half2(__float2half(v.z), __float2half(v.w));
    }
}

// build interleaved Wcat (row 2j = Wv[j], row 2j+1 = Wu[j]) fp16 hi/lo + bcat
__global__ void cat_kernel(const float* __restrict__ Wv, const float* __restrict__ Wu,
                           const float* __restrict__ bv, const float* __restrict__ bu,
                           __half* __restrict__ whi, __half* __restrict__ wlo,
                           float* __restrict__ bcat) {
    int i = blockIdx.x * blockDim.x + threadIdx.x;
    if (i < 2 * D_DIM * L_DIM) {
        int row = i >> 9, k = i & 511;
        int j = row >> 1, e = row & 1;
        float v = e ? Wu[j * L_DIM + k] : Wv[j * L_DIM + k];
        __half h = __float2half(v);
        whi[i] = h;
        wlo[i] = __float2half(v - __half2float(h));
    }
    if (i < 2 * D_DIM) {
        int j = i >> 1, e = i & 1;
        bcat[i] = e ? bu[j] : bv[j];
    }
}

// ===== GEMM: 256 threads, CTA tile 128x256, warp grid 2x4, warp tile 64x64, BK=32 =====
// A tile 128x32 = 8KB, B tile 256x32 = 16KB; 64B rows, swizzle col16 ^= (row>>1)&3
#define TA32 8192
#define TBB32 16384
#define G1_SMEM (2 * TA32 + 3 * TBB32)    // conv x 2x8KB + B 3x16KB = 64KB
#define G2_SMEM (3 * (TA32 + 2 * TBB32))  // 3 x (A 8KB + Bhi/Blo 32KB) = 120KB

__global__ __launch_bounds__(256, 1)
void gemm1_fused(const float* __restrict__ X,
                 const __half* __restrict__ B16,
                 const float* __restrict__ bias,
                 __half* __restrict__ OutH)
{
    extern __shared__ __align__(1024) unsigned char dsm[];
    const int tid  = threadIdx.x;
    const int bn   = blockIdx.x;                   // 0..1
    const int bm   = blockIdx.y;
    const int wid  = tid >> 5, lane = tid & 31;
    const int wm   = wid & 1, wn = wid >> 1;       // 2(M) x 4(N)
    const int m0   = bm * 128, n0 = bn * 256;
    const int K = E_DIM, NC = E_DIM / 32;          // 32
    const uint32_t sb = smem_u32(dsm);
    const uint32_t convB = sb;                     // conv[c]: 8KB each
    const uint32_t bBase = sb + 2 * TA32;

    auto loadB = [&](int s, int k0) {
        uint32_t dst = bBase + s * TBB32;
#pragma unroll
        for (int it = 0; it < 4; it++) {
            int q = tid + it * 256;                // 256 rows x 4 chunks
            int row = q >> 2;
            int c16 = q & 3;
            uint32_t off = (uint32_t)(row * 64) + (uint32_t)((c16 ^ ((row >> 1) & 3)) << 4);
            cp16(dst + off, (const char*)B16 + ((size_t)(n0 + row) * K + k0 + c16 * 8) * 2);
        }
        asm volatile("cp.async.commit_group;" ::: "memory");
    };

    // register-staged x conversion: 128 rows x 32 fp32 = 16KB; 16 floats/thread
    float4 xr[4];
    const int xrow = tid >> 1;                 // 2 threads per row
    const int xseg2 = (tid & 1) * 2;           // segs {0,1} or {2,3} (8 floats each)
    auto ldgX = [&](int k0) {
        const float* src = X + (size_t)(m0 + xrow) * K + k0 + xseg2 * 8;
#pragma unroll
        for (int j = 0; j < 4; j++) xr[j] = *(const float4*)(src + j * 4);
    };
    auto stsX = [&](int buf) {
        unsigned char* hp = dsm + buf * TA32;
        const uint32_t sw = (uint32_t)((xrow >> 1) & 3);
#pragma unroll
        for (int s2 = 0; s2 < 2; s2++) {
            int seg = xseg2 + s2;
            float4 a = xr[2 * s2], b = xr[2 * s2 + 1];
            uint32_t off = (uint32_t)(xrow * 64) + (uint32_t)(((uint32_t)seg ^ sw) << 4);
            uint4 hv;
            hv.x = packh2(a.x, a.y); hv.y = packh2(a.z, a.w);
            hv.z = packh2(b.x, b.y); hv.w = packh2(b.z, b.w);
            *(uint4*)(hp + off) = hv;
        }
    };

    const int aRow = wm * 64 + (lane & 15);
    const uint32_t aK  = ((lane >> 4) & 1) * 16;
    const uint32_t aSw = (uint32_t)((aRow >> 1) & 3) << 4;
    const int bRow = wn * 64 + (lane & 7) + (((lane >> 4) & 1) << 3);
    const uint32_t bK  = ((lane >> 3) & 1) * 16;
    const uint32_t bSw = (uint32_t)((bRow >> 1) & 3) << 4;

    float acc[4][8][4];
#pragma unroll
    for (int mi = 0; mi < 4; mi++)
#pragma unroll
        for (int ni = 0; ni < 8; ni++)
#pragma unroll
            for (int e = 0; e < 4; e++) acc[mi][ni][e] = 0.f;

    loadB(0, 0);
    loadB(1, 32);
    ldgX(0);
    stsX(0);
    ldgX(32);

    for (int i = 0; i < NC; i++) {
        if (i + 1 < NC) asm volatile("cp.async.wait_group 1;" ::: "memory");
        else            asm volatile("cp.async.wait_group 0;" ::: "memory");
        __syncthreads();
        if (i + 2 < NC) loadB((i + 2) % 3, (i + 2) * 32);
        if (i + 1 < NC) stsX((i + 1) & 1);
        if (i + 2 < NC) ldgX((i + 2) * 32);

        const uint32_t sA = convB + (i & 1) * TA32;
        const uint32_t sB = bBase + (i % 3) * TBB32;

#pragma unroll
        for (int ks = 0; ks < 2; ks++) {
            uint32_t aa[4][4], bb[4][4];
            const uint32_t akc = (uint32_t)(ks * 32) + aK;
            const uint32_t bkc = (uint32_t)(ks * 32) + bK;
#pragma unroll
            for (int mi = 0; mi < 4; mi++) {
                uint32_t ro = (uint32_t)((aRow + mi * 16) * 64) + (akc ^ aSw);
                ldsm4(aa[mi], sA + ro);
            }
#pragma unroll
            for (int nj = 0; nj < 4; nj++) {
                uint32_t ro = (uint32_t)((bRow + nj * 16) * 64) + (bkc ^ bSw);
                ldsm4(bb[nj], sB + ro);
            }
#pragma unroll
            for (int mi = 0; mi < 4; mi++)
#pragma unroll
                for (int nj = 0; nj < 4; nj++) {
                    mma16816h(acc[mi][2 * nj],     aa[mi], &bb[nj][0]);
                    mma16816h(acc[mi][2 * nj + 1], aa[mi], &bb[nj][2]);
                }
        }
    }

    // epilogue: relu(acc+bias) -> single fp16
    const int rBase = m0 + wm * 64 + (lane >> 2);
    const int cBase = n0 + wn * 64 + 2 * (lane & 3);
#pragma unroll
    for (int mi = 0; mi < 4; mi++) {
#pragma unroll
        for (int ni = 0; ni < 8; ni++) {
            const int c = cBase + ni * 8;
            const float b0 = bias[c], b1 = bias[c + 1];
#pragma unroll
            for (int half = 0; half < 2; half++) {
                const int r = rBase + mi * 16 + half * 8;
                float v0 = fmaxf(acc[mi][ni][2 * half]     + b0, 0.f);
                float v1 = fmaxf(acc[mi][ni][2 * half + 1] + b1, 0.f);
                size_t o = ((size_t)r * 512 + c) >> 1;
                ((__half2*)OutH)[o] = __halves2half2(__float2half(v0), __float2half(v1));
            }
        }
    }
}

// GEMM2: A = h fp16 (single), B = Wcat fp16 hi/lo. 2 products. CTA 128x256.
__global__ __launch_bounds__(256, 1)
void gemm2_hmma(const __half* __restrict__ A16,
                const __half* __restrict__ Bhi, const __half* __restrict__ Blo,
                const float* __restrict__ bias, const float* __restrict__ Wa)
{
    extern __shared__ __align__(1024) unsigned char dsm[];
    const int tid  = threadIdx.x;
    const int bn   = blockIdx.x;                   // 0..1
    const int bm   = blockIdx.y;
    const int wid  = tid >> 5, lane = tid & 31;
    const int wm   = wid & 1, wn = wid >> 1;
    const int m0   = bm * 128, n0 = bn * 256;
    const int K = L_DIM, NC = L_DIM / 32;          // 16
    const uint32_t sb = smem_u32(dsm);
    const int STG = TA32 + 2 * TBB32;              // A 8KB + Bhi 16KB + Blo 16KB

    auto loadA = [&](uint32_t dst, int k0) {
#pragma unroll
        for (int it = 0; it < 2; it++) {
            int q = tid + it * 256;                // 128 rows x 4 chunks
            int row = q >> 2;
            int c16 = q & 3;
            uint32_t off = (uint32_t)(row * 64) + (uint32_t)((c16 ^ ((row >> 1) & 3)) << 4);
            cp16(dst + off, (const char*)A16 + ((size_t)(m0 + row) * K + k0 + c16 * 8) * 2);
        }
    };
    auto loadBt = [&](uint32_t dst, const __half* p, int k0) {
#pragma unroll
        for (int it = 0; it < 4; it++) {
            int q = tid + it * 256;                // 256 rows x 4 chunks
            int row = q >> 2;
            int c16 = q & 3;
            uint32_t off = (uint32_t)(row * 64) + (uint32_t)((c16 ^ ((row >> 1) & 3)) << 4);
            cp16(dst + off, (const char*)p + ((size_t)(n0 + row) * K + k0 + c16 * 8) * 2);
        }
    };
    auto loadStage = [&](int s, int k0) {
        uint32_t st = sb + s * STG;
        loadA(st, k0);
        loadBt(st + TA32,          Bhi, k0);
        loadBt(st + TA32 + TBB32,  Blo, k0);
        asm volatile("cp.async.commit_group;" ::: "memory");
    };

    const int aRow = wm * 64 + (lane & 15);
    const uint32_t aK  = ((lane >> 4) & 1) * 16;
    const uint32_t aSw = (uint32_t)((aRow >> 1) & 3) << 4;
    const int bRow = wn * 64 + (lane & 7) + (((lane >> 4) & 1) << 3);
    const uint32_t bK  = ((lane >> 3) & 1) * 16;
    const uint32_t bSw = (uint32_t)((bRow >> 1) & 3) << 4;

    float acc[4][8][4];
#pragma unroll
    for (int mi = 0; mi < 4; mi++)
#pragma unroll
        for (int ni = 0; ni < 8; ni++)
#pragma unroll
            for (int e = 0; e < 4; e++) acc[mi][ni][e] = 0.f;

    loadStage(0, 0);
    loadStage(1, 32);

    for (int i = 0; i < NC; i++) {
        if (i + 1 < NC) asm volatile("cp.async.wait_group 1;" ::: "memory");
        else            asm volatile("cp.async.wait_group 0;" ::: "memory");
        __syncthreads();
        if (i + 2 < NC) loadStage((i + 2) % 3, (i + 2) * 32);

        const uint32_t st  = sb + (i % 3) * STG;
        const uint32_t sA  = st;
        const uint32_t sBh = st + TA32, sBl = st + TA32 + TBB32;

#pragma unroll
        for (int ks = 0; ks < 2; ks++) {
            uint32_t aa[4][4], bb[4][4], bro[4];
            const uint32_t akc = (uint32_t)(ks * 32) + aK;
            const uint32_t bkc = (uint32_t)(ks * 32) + bK;
#pragma unroll
            for (int mi = 0; mi < 4; mi++) {
                uint32_t ro = (uint32_t)((aRow + mi * 16) * 64) + (akc ^ aSw);
                ldsm4(aa[mi], sA + ro);
            }
#pragma unroll
            for (int nj = 0; nj < 4; nj++) {
                bro[nj] = (uint32_t)((bRow + nj * 16) * 64) + (bkc ^ bSw);
                ldsm4(bb[nj], sBh + bro[nj]);
            }
#pragma unroll
            for (int mi = 0; mi < 4; mi++)
#pragma unroll
                for (int nj = 0; nj < 4; nj++) {
                    mma16816h(acc[mi][2 * nj],     aa[mi], &bb[nj][0]);
                    mma16816h(acc[mi][2 * nj + 1], aa[mi], &bb[nj][2]);
                }
#pragma unroll
            for (int nj = 0; nj < 4; nj++) ldsm4(bb[nj], sBl + bro[nj]);
#pragma unroll
            for (int mi = 0; mi < 4; mi++)
#pragma unroll
                for (int nj = 0; nj < 4; nj++) {
                    mma16816h(acc[mi][2 * nj],     aa[mi], &bb[nj][0]);
                    mma16816h(acc[mi][2 * nj + 1], aa[mi], &bb[nj][2]);
                }
        }
    }

    // fused gated-attention projection epilogue
    const int rBase = m0 + wm * 64 + (lane >> 2);
    const int cBase = n0 + wn * 64 + 2 * (lane & 3);
#pragma unroll
    for (int mi = 0; mi < 4; mi++) {
#pragma unroll
        for (int half = 0; half < 2; half++) {
            const int r = rBase + mi * 16 + half * 8;
            float s0 = 0.f, s1 = 0.f;
#pragma unroll
            for (int ni = 0; ni < 8; ni++) {
                const int c = cBase + ni * 8;
                float v0 = acc[mi][ni][2 * half]     + bias[c];
                float v1 = acc[mi][ni][2 * half + 1] + bias[c + 1];
                float gg = tanhf(v0) / (1.f + expf(-v1));
                const int gc = c >> 1;
                s0 = fmaf(gg, Wa[gc], s0);
                s1 = fmaf(gg, Wa[D_DIM + gc], s1);
            }
            s0 += __shfl_xor_sync(0xFFFFFFFFu, s0, 1);
            s0 += __shfl_xor_sync(0xFFFFFFFFu, s0, 2);
            s1 += __shfl_xor_sync(0xFFFFFFFFu, s1, 1);
            s1 += __shfl_xor_sync(0xFFFFFFFFu, s1, 2);
            if ((lane & 3) == 0) {
                atomicAdd(&g_A[2 * r],     s0);
                atomicAdd(&g_A[2 * r + 1], s1);
            }
        }
    }
}

// ---------------- finalize: +ba, raw_attention out, per-class max, histogram ----------------
__global__ void finalize_kernel(const float* __restrict__ ba, const int* __restrict__ labelPtr,
                                float* __restrict__ out_att)
{
    __shared__ unsigned sk0, sk1;
    if (threadIdx.x == 0) { sk0 = 0u; sk1 = 0u; }
    __syncthreads();
    int i = blockIdx.x * blockDim.x + threadIdx.x;
    int lab = labelPtr ? *labelPtr : 0;
    float a0 = g_A[2 * i] + ba[0];
    float a1 = g_A[2 * i + 1] + ba[1];
    g_A[2 * i] = a0; g_A[2 * i + 1] = a1;
    out_att[i] = a0;
    out_att[NROWS + i] = a1;
    atomicMax(&sk0, monoKey(a0));
    atomicMax(&sk1, monoKey(a1));
    float sel = lab ? a1 : a0;
    atomicAdd(&g_hist[monoKey(sel) >> 18], 1);
    __syncthreads();
    if (threadIdx.x == 0) {
        atomicMax(&g_maxkey[0], sk0);
        atomicMax(&g_maxkey[1], sk1);
    }
}

// ---------------- fused softmax-weighted bag accumulation (h fp16) ----------------
__global__ void bag_kernel()
{
    const int t = threadIdx.x;
    const int rowsPerBlock = NROWS / gridDim.x;
    const int r0 = blockIdx.x * rowsPerBlock;
    const float m0 = monoDecode(g_maxkey[0]);
    const float m1 = monoDecode(g_maxkey[1]);

    float a00 = 0.f, a01 = 0.f, a10 = 0.f, a11 = 0.f;
    float z0 = 0.f, z1 = 0.f;
    for (int r = r0; r < r0 + rowsPerBlock; r++) {
        float w0 = expf(g_A[2 * r]     - m0);
        float w1 = expf(g_A[2 * r + 1] - m1);
        const __half2* hp = (const __half2*)(g_h16 + (size_t)r * L_DIM);
        __half2 a2 = hp[t];
        float v0 = __low2float(a2);
        float v1 = __high2float(a2);
        a00 = fmaf(w0, v0, a00); a01 = fmaf(w0, v1, a01);
        a10 = fmaf(w1, v0, a10); a11 = fmaf(w1, v1, a11);
        if (t == 0) { z0 += w0; z1 += w1; }
    }
    atomicAdd(&g_bag[2 * t], a00);
    atomicAdd(&g_bag[2 * t + 1], a01);
    atomicAdd(&g_bag[L_DIM + 2 * t], a10);
    atomicAdd(&g_bag[L_DIM + 2 * t + 1], a11);
    if (t == 0) { atomicAdd(&g_Z[0], z0); atomicAdd(&g_Z[1], z1); }
}

// ---------------- top-k machinery ----------------
__global__ void scan_kernel()
{
    __shared__ int csum[256];
    int t = threadIdx.x;
    int s = 0;
    for (int b = t * 64; b < t * 64 + 64; b++) s += g_hist[b];
    csum[t] = s;
    __syncthreads();
    if (t == 0) {
        int cum = 0, binhi = 0;
        for (int c = 255; c >= 0; c--) {
            if (cum + csum[c] >= NI) {
                for (int b = c * 64 + 63; b >= c * 64; b--) {
                    cum += g_hist[b];
                    if (cum >= NI) { binhi = b; break; }
                }
                break;
            }
            cum += csum[c];
        }
        g_binhi = binhi;
        cum = 0; int binlo = 16383;
        for (int c = 0; c < 256; c++) {
            if (cum + csum[c] >= NI) {
                for (int b = c * 64; b < c * 64 + 64; b++) {
                    cum += g_hist[b];
                    if (cum >= NI) { binlo = b; break; }
                }
                break;
            }
            cum += csum[c];
        }
        g_binlo = binlo;
        g_nhi = 0; g_nlo = 0;
    }
}

__global__ void cand_kernel(const int* __restrict__ labelPtr)
{
    int lab = labelPtr ? *labelPtr : 0;
    int binhi = g_binhi, binlo = g_binlo;
    for (int i = blockIdx.x * blockDim.x + threadIdx.x; i < NROWS; i += gridDim.x * blockDim.x) {
        float v = g_A[2 * i + lab];
        unsigned key = monoKey(v) >> 18;
        if ((int)key >= binhi) {
            int p = atomicAdd(&g_nhi, 1);
            g_chv[p] = v; g_chi[p] = i;
        }
        if ((int)key <= binlo) {
            int p = atomicAdd(&g_nlo, 1);
            g_clv[p] = v; g_cli[p] = i;
        }
    }
}

__global__ void select_kernel()
{
    __shared__ float sv[256];
    __shared__ int   si[256];
    __shared__ int   sp[256];
    const int t = threadIdx.x;
    const float NEG_INF = __int_as_float(0xFF800000);
    const float POS_INF = __int_as_float(0x7F800000);
    int nhi = g_nhi, nlo = g_nlo;

    for (int it = 0; it < NI; it++) {
        float bv = NEG_INF; int bi = 0x7FFFFFFF; int bp = -1;
        for (int p = t; p < nhi; p += 256) {
            float v = g_chv[p]; int idx = g_chi[p];
            if (v > bv || (v == bv && idx < bi)) { bv = v; bi = idx; bp = p; }
        }
        sv[t] = bv; si[t] = bi; sp[t] = bp;
        __syncthreads();
        for (int s = 128; s; s >>= 1) {
            if (t < s) {
                if (sv[t + s] > sv[t] || (sv[t + s] == sv[t] && si[t + s] < si[t])) {
                    sv[t] = sv[t + s]; si[t] = si[t + s]; sp[t] = sp[t + s];
                }
            }
            __syncthreads();
        }
        if (t == 0) { g_inst[it] = si[0]; g_chv[sp[0]] = NEG_INF; }
        __syncthreads();
    }
    for (int it = 0; it < NI; it++) {
        float bv = POS_INF; int bi = 0x7FFFFFFF; int bp = -1;
        for (int p = t; p < nlo; p += 256) {
            float v = g_clv[p]; int idx = g_cli[p];
            if (v < bv || (v == bv && idx < bi)) { bv = v; bi = idx; bp = p; }
        }
        sv[t] = bv; si[t] = bi; sp[t] = bp;
        __syncthreads();
        for (int s = 128; s; s >>= 1) {
            if (t < s) {
                if (sv[t + s] < sv[t] || (sv[t + s] == sv[t] && si[t + s] < si[t])) {
                    sv[t] = sv[t + s]; si[t] = si[t + s]; sp[t] = sp[t + s];
                }
            }
            __syncthreads();
        }
        if (t == 0) { g_inst[NI + it] = si[0]; g_clv[sp[0]] = POS_INF; }
        __syncthreads();
    }
}

// ---------------- instance loss (h fp16) ----------------
__global__ void loss_kernel(const int* __restrict__ labelPtr,
                            const float* __restrict__ Winst, const float* __restrict__ binst,
                            float* __restrict__ out_loss)
{
    __shared__ float sl[4];
    int lab = labelPtr ? *labelPtr : 0;
    const float* W0 = Winst + ((size_t)lab * 2 + 0) * L_DIM;
    const float* W1 = Winst + ((size_t)lab * 2 + 1) * L_DIM;
    float b0 = binst[lab * 2], b1 = binst[lab * 2 + 1];

    int warp = threadIdx.x >> 5, lane = threadIdx.x & 31;
    float lsum = 0.f;
    for (int r = warp; r < 2 * NI; r += 4) {
        const __half* hp = g_h16 + (size_t)g_inst[r] * L_DIM;
        float s0 = 0.f, s1 = 0.f;
        for (int k = lane; k < L_DIM; k += 32) {
            float v = __half2float(hp[k]);
            s0 = fmaf(v, W0[k], s0);
            s1 = fmaf(v, W1[k], s1);
        }
#pragma unroll
        for (int o = 16; o; o >>= 1) {
            s0 += __shfl_xor_sync(0xFFFFFFFFu, s0, o);
            s1 += __shfl_xor_sync(0xFFFFFFFFu, s1, o);
        }
        if (lane == 0) {
            float l0 = s0 + b0, l1 = s1 + b1;
            int tgt = (r < NI) ? 1 : 0;
            float u0 = l0 + ((tgt != 0) ? 1.f : 0.f);
            float u1 = l1 + ((tgt != 1) ? 1.f : 0.f);
            float m = fmaxf(u0, u1);
            float lse = m + logf(expf(u0 - m) + expf(u1 - m));
            float sy = (tgt == 0) ? l0 : l1;
            lsum += lse - sy;
        }
    }
    if (lane == 0) sl[warp] = lsum;
    __syncthreads();
    if (threadIdx.x == 0)
        *out_loss = (sl[0] + sl[1] + sl[2] + sl[3]) * (1.f / (2 * NI));
}

// ---------------- bag logits + softmax ----------------
__global__ void final_kernel(const float* __restrict__ Wbag, const float* __restrict__ bbag,
                             float* __restrict__ out)
{
    __shared__ float lg[2];
    int warp = threadIdx.x >> 5, lane = threadIdx.x & 31;
    if (warp < 2) {
        float s = 0.f;
        for (int k = lane; k < L_DIM; k += 32)
            s = fmaf(g_bag[warp * L_DIM + k], Wbag[warp * L_DIM + k], s);
#pragma unroll
        for (int o = 16; o; o >>= 1) s += __shfl_xor_sync(0xFFFFFFFFu, s, o);
        if (lane == 0) lg[warp] = s / g_Z[warp] + bbag[warp];
    }
    __syncthreads();
    if (threadIdx.x == 0) {
        float l0 = lg[0], l1 = lg[1];
        out[0] = l0; out[1] = l1;
        float m = fmaxf(l0, l1);
        float e0 = expf(l0 - m), e1 = expf(l1 - m);
        float s = e0 + e1;
        out[2] = e0 / s; out[3] = e1 / s;
    }
}

// ---------------- launch ----------------
extern "C" void kernel_launch(void* const* d_in, const int* in_sizes, int n_in,
                              void* d_out, int out_size)
{
    const int off = (n_in >= 14) ? 1 : 0;
    const float* x     = (const float*)d_in[0];
    const int*   label = (n_in >= 14) ? (const int*)d_in[1] : nullptr;
    const float* Wc    = (const float*)d_in[1 + off];
    const float* bc    = (const float*)d_in[2 + off];
    const float* Wv    = (const float*)d_in[3 + off];
    const float* bv    = (const float*)d_in[4 + off];
    const float* Wu    = (const float*)d_in[5 + off];
    const float* bu    = (const float*)d_in[6 + off];
    const float* Wa    = (const float*)d_in[7 + off];
    const float* ba    = (const float*)d_in[8 + off];
    const float* Winst = (const float*)d_in[9 + off];
    const float* binst = (const float*)d_in[10 + off];
    const float* Wbag  = (const float*)d_in[11 + off];
    const float* bbag  = (const float*)d_in[12 + off];
    float* out = (float*)d_out;

    void* p;
    cudaGetSymbolAddress(&p, g_h16);  __half* h16 = (__half*)p;
    cudaGetSymbolAddress(&p, g_wc16); __half* wc16 = (__half*)p;
    cudaGetSymbolAddress(&p, g_wthi); __half* wthi = (__half*)p;
    cudaGetSymbolAddress(&p, g_wtlo); __half* wtlo = (__half*)p;
    cudaGetSymbolAddress(&p, g_bcat); float* bcat = (float*)p;

    cudaFuncSetAttribute(gemm1_fused, cudaFuncAttributeMaxDynamicSharedMemorySize, G1_SMEM);
    cudaFuncSetAttribute(gemm2_hmma,  cudaFuncAttributeMaxDynamicSharedMemorySize, G2_SMEM);

    // launches #1..#3 (gemm1 stays launch #4 for ncu)
    init_kernel<<<1024, 256>>>();
    cvtw_kernel<<<256, 256>>>((const float4*)Wc, (__half2*)wc16, (L_DIM * E_DIM) / 4);
    cat_kernel<<<(2 * D_DIM * L_DIM + 255) / 256, 256>>>(Wv, Wu, bv, bu, wthi, wtlo, bcat);

    // GEMM1 (launch #4): h = relu(x @ Wc^T + bc) -> fp16 (CTA 128x256, halved x traffic)
    gemm1_fused<<<dim3(2, NROWS / 128), 256, G1_SMEM>>>(x, wc16, bc, h16);

    // GEMM2+3 + attention fused (fp16 2-product, CTA 128x256)
    gemm2_hmma<<<dim3(2, NROWS / 128), 256, G2_SMEM>>>(h16, wthi, wtlo, bcat, Wa);

    finalize_kernel<<<NROWS / 256, 256>>>(ba, label, out + 4);
    scan_kernel<<<1, 256>>>();
    cand_kernel<<<NROWS / 256, 256>>>(label);
    select_kernel<<<1, 256>>>();
    loss_kernel<<<1, 128>>>(label, Winst, binst, out + 4 + 2 * NROWS);
    bag_kernel<<<512, 256>>>();
    final_kernel<<<1, 64>>>(Wbag, bbag, out);
}

// round 15
// speedup vs baseline: 1.1988x; 1.1988x over previous
#include <cuda_runtime.h>
#include <cuda_bf16.h>
#include <cuda_fp16.h>
#include <math.h>
#include <stdint.h>

#define NROWS 131072
#define E_DIM 1024
#define L_DIM 512
#define D_DIM 256
#define NI    50

// ---------------- device scratch (allocation-free rule) ----------------
__device__ __half g_h16[(size_t)NROWS * L_DIM];   // h as single fp16
__device__ __half g_wc16[L_DIM * E_DIM];          // Wc single fp16
__device__ __half g_wt16[2 * D_DIM * L_DIM];      // Wcat single fp16
__device__ float g_bcat[2 * D_DIM];
__device__ float g_A[(size_t)NROWS * 2];
__device__ int      g_hist[16384];
__device__ unsigned g_maxkey[2];
__device__ float    g_Z[2];
__device__ float    g_bag[2 * L_DIM];
__device__ int      g_binhi, g_binlo;
__device__ int      g_nhi, g_nlo;
__device__ float g_chv[NROWS]; __device__ int g_chi[NROWS];
__device__ float g_clv[NROWS]; __device__ int g_cli[NROWS];
__device__ int   g_inst[2 * NI];

// ---------------- PTX helpers ----------------
__device__ __forceinline__ uint32_t smem_u32(const void* p) {
    uint32_t a;
    asm("{ .reg .u64 t; cvta.to.shared.u64 t, %1; cvt.u32.u64 %0, t; }" : "=r"(a) : "l"(p));
    return a;
}
__device__ __forceinline__ void cp16(uint32_t s, const void* g) {
    asm volatile("cp.async.cg.shared.global [%0], [%1], 16;" :: "r"(s), "l"(g));
}
__device__ __forceinline__ void ldsm4(uint32_t* r, uint32_t addr) {
    asm volatile("ldmatrix.sync.aligned.m8n8.x4.shared.b16 {%0,%1,%2,%3}, [%4];"
                 : "=r"(r[0]), "=r"(r[1]), "=r"(r[2]), "=r"(r[3]) : "r"(addr));
}
__device__ __forceinline__ void mma16816h(float* c, const uint32_t* a, const uint32_t* b) {
    asm volatile(
        "mma.sync.aligned.m16n8k16.row.col.f32.f16.f16.f32 "
        "{%0,%1,%2,%3}, {%4,%5,%6,%7}, {%8,%9}, {%0,%1,%2,%3};"
        : "+f"(c[0]), "+f"(c[1]), "+f"(c[2]), "+f"(c[3])
        : "r"(a[0]), "r"(a[1]), "r"(a[2]), "r"(a[3]), "r"(b[0]), "r"(b[1]));
}

// monotone float <-> uint key
__device__ __forceinline__ unsigned monoKey(float f) {
    unsigned u = __float_as_uint(f);
    return (u & 0x80000000u) ? ~u : (u | 0x80000000u);
}
__device__ __forceinline__ float monoDecode(unsigned k) {
    unsigned u = (k & 0x80000000u) ? (k & 0x7FFFFFFFu) : ~k;
    return __uint_as_float(u);
}

__device__ __forceinline__ uint32_t packh2(float a, float b) {
    __half2 t = __halves2half2(__float2half(a), __float2half(b));
    return *(uint32_t*)&t;
}

// ---------------- init ----------------
__global__ void init_kernel() {
    int i = blockIdx.x * blockDim.x + threadIdx.x;
    if (i < 2 * NROWS) g_A[i] = 0.f;
    if (i < 16384) g_hist[i] = 0;
    if (i < 2 * L_DIM) g_bag[i] = 0.f;
    if (i < 2) { g_Z[i] = 0.f; g_maxkey[i] = 0u; }
    if (i == 0) { g_nhi = 0; g_nlo = 0; }
}

// ---------------- fp32 -> fp16 convert (Wc single) ----------------
__global__ void cvtw_kernel(const float4* __restrict__ in, __half2* __restrict__ out16, int n4) {
    int i = blockIdx.x * blockDim.x + threadIdx.x;
    int stride = gridDim.x * blockDim.x;
    for (; i < n4; i += stride) {
        float4 v = in[i];
        out16[2 * i]     = __halves2half2(__float2half(v.x), __float2half(v.y));
        out16[2 * i + 1] = __halves2half2(__float2half(v.z), __float2half(v.w));
    }
}

// build interleaved Wcat (row 2j = Wv[j], row 2j+1 = Wu[j]) single fp16 + bcat
__global__ void cat_kernel(const float* __restrict__ Wv, const float* __restrict__ Wu,
                           const float* __restrict__ bv, const float* __restrict__ bu,
                           __half* __restrict__ w16, float* __restrict__ bcat) {
    int i = blockIdx.x * blockDim.x + threadIdx.x;
    if (i < 2 * D_DIM * L_DIM) {
        int row = i >> 9, k = i & 511;
        int j = row >> 1, e = row & 1;
        float v = e ? Wu[j * L_DIM + k] : Wv[j * L_DIM + k];
        w16[i] = __float2half(v);
    }
    if (i < 2 * D_DIM) {
        int j = i >> 1, e = i & 1;
        bcat[i] = e ? bu[j] : bv[j];
    }
}

// ===== GEMM config (R13 shape): 128 threads, warp grid 2x2, warp tile 64x64, BK=32 =====
// tile = 128 rows x 32 x 2B = 8KB, row stride 64B, swizzle: col16 ^= (row>>1)&3
#define TB32 8192
#define G1_SMEM (2 * TB32 + 3 * TB32)     // conv x 2x8KB + B 3x8KB = 40KB
#define G2_SMEM (3 * 2 * TB32)            // 3 stages x (A, B) = 48KB

__global__ __launch_bounds__(128, 2)
void gemm1_fused(const float* __restrict__ X,
                 const __half* __restrict__ B16,
                 const float* __restrict__ bias,
                 __half* __restrict__ OutH)
{
    extern __shared__ __align__(1024) unsigned char dsm[];
    const int tid  = threadIdx.x;
    const int bn   = blockIdx.x;
    const int bm   = blockIdx.y;
    const int wid  = tid >> 5, lane = tid & 31;
    const int wm   = wid & 1, wn = wid >> 1;       // 2x2 warp grid
    const int m0   = bm * 128, n0 = bn * 128;
    const int K = E_DIM, NC = E_DIM / 32;          // 32
    const uint32_t sb = smem_u32(dsm);
    const uint32_t convB = sb;                     // conv[c]: 8KB each
    const uint32_t bBase = sb + 2 * TB32;

    auto loadB = [&](int s, int k0) {
        uint32_t dst = bBase + s * TB32;
#pragma unroll
        for (int it = 0; it < 4; it++) {
            int q = tid + it * 128;
            int row = q >> 2;
            int c16 = q & 3;
            uint32_t off = (uint32_t)(row * 64) + (uint32_t)((c16 ^ ((row >> 1) & 3)) << 4);
            cp16(dst + off, (const char*)B16 + ((size_t)(n0 + row) * K + k0 + c16 * 8) * 2);
        }
        asm volatile("cp.async.commit_group;" ::: "memory");
    };

    // --- register-staged x conversion ---
    float4 xr[8];
    const int xrow = tid >> 1;
    const int xseg2 = (tid & 1) * 2;
    auto ldgX = [&](int k0) {
        const float* src = X + (size_t)(m0 + xrow) * K + k0 + xseg2 * 8;
#pragma unroll
        for (int j = 0; j < 4; j++) xr[2 * j]     = *(const float4*)(src + j * 4);
        const float* src2 = X + (size_t)(m0 + 64 + xrow) * K + k0 + xseg2 * 8;
#pragma unroll
        for (int j = 0; j < 4; j++) xr[2 * j + 1] = *(const float4*)(src2 + j * 4);
    };
    auto stsX = [&](int buf) {
        unsigned char* hp = dsm + buf * TB32;
#pragma unroll
        for (int half = 0; half < 2; half++) {
            int row = xrow + half * 64;
            const uint32_t sw = (uint32_t)((row >> 1) & 3);
#pragma unroll
            for (int s2 = 0; s2 < 2; s2++) {
                int seg = xseg2 + s2;
                float4 a = xr[(2 * s2) * 2 + half];
                float4 b = xr[(2 * s2 + 1) * 2 + half];
                uint32_t off = (uint32_t)(row * 64) + (uint32_t)(((uint32_t)seg ^ sw) << 4);
                uint4 hv;
                hv.x = packh2(a.x, a.y); hv.y = packh2(a.z, a.w);
                hv.z = packh2(b.x, b.y); hv.w = packh2(b.z, b.w);
                *(uint4*)(hp + off) = hv;
            }
        }
    };

    const int aRow = wm * 64 + (lane & 15);
    const uint32_t aK  = ((lane >> 4) & 1) * 16;
    const uint32_t aSw = (uint32_t)((aRow >> 1) & 3) << 4;
    const int bRow = wn * 64 + (lane & 7) + (((lane >> 4) & 1) << 3);
    const uint32_t bK  = ((lane >> 3) & 1) * 16;
    const uint32_t bSw = (uint32_t)((bRow >> 1) & 3) << 4;

    float acc[4][8][4];
#pragma unroll
    for (int mi = 0; mi < 4; mi++)
#pragma unroll
        for (int ni = 0; ni < 8; ni++)
#pragma unroll
            for (int e = 0; e < 4; e++) acc[mi][ni][e] = 0.f;

    loadB(0, 0);
    loadB(1, 32);
    ldgX(0);
    stsX(0);
    ldgX(32);

    for (int i = 0; i < NC; i++) {
        if (i + 1 < NC) asm volatile("cp.async.wait_group 1;" ::: "memory");
        else            asm volatile("cp.async.wait_group 0;" ::: "memory");
        __syncthreads();
        if (i + 2 < NC) loadB((i + 2) % 3, (i + 2) * 32);
        if (i + 1 < NC) stsX((i + 1) & 1);
        if (i + 2 < NC) ldgX((i + 2) * 32);

        const uint32_t sA = convB + (i & 1) * TB32;
        const uint32_t sB = bBase + (i % 3) * TB32;

#pragma unroll
        for (int ks = 0; ks < 2; ks++) {
            uint32_t aa[4][4], bb[4][4];
            const uint32_t akc = (uint32_t)(ks * 32) + aK;
            const uint32_t bkc = (uint32_t)(ks * 32) + bK;
#pragma unroll
            for (int mi = 0; mi < 4; mi++) {
                uint32_t ro = (uint32_t)((aRow + mi * 16) * 64) + (akc ^ aSw);
                ldsm4(aa[mi], sA + ro);
            }
#pragma unroll
            for (int nj = 0; nj < 4; nj++) {
                uint32_t ro = (uint32_t)((bRow + nj * 16) * 64) + (bkc ^ bSw);
                ldsm4(bb[nj], sB + ro);
            }
#pragma unroll
            for (int mi = 0; mi < 4; mi++)
#pragma unroll
                for (int nj = 0; nj < 4; nj++) {
                    mma16816h(acc[mi][2 * nj],     aa[mi], &bb[nj][0]);
                    mma16816h(acc[mi][2 * nj + 1], aa[mi], &bb[nj][2]);
                }
        }
    }

    // epilogue: relu(acc+bias) -> single fp16
    const int rBase = m0 + wm * 64 + (lane >> 2);
    const int cBase = n0 + wn * 64 + 2 * (lane & 3);
#pragma unroll
    for (int mi = 0; mi < 4; mi++) {
#pragma unroll
        for (int ni = 0; ni < 8; ni++) {
            const int c = cBase + ni * 8;
            const float b0 = bias[c], b1 = bias[c + 1];
#pragma unroll
            for (int half = 0; half < 2; half++) {
                const int r = rBase + mi * 16 + half * 8;
                float v0 = fmaxf(acc[mi][ni][2 * half]     + b0, 0.f);
                float v1 = fmaxf(acc[mi][ni][2 * half + 1] + b1, 0.f);
                size_t o = ((size_t)r * 512 + c) >> 1;
                ((__half2*)OutH)[o] = __halves2half2(__float2half(v0), __float2half(v1));
            }
        }
    }
}

// GEMM2: A = h fp16, B = Wcat fp16, single product.
__global__ __launch_bounds__(128, 2)
void gemm2_hmma(const __half* __restrict__ A16,
                const __half* __restrict__ B16,
                const float* __restrict__ bias, const float* __restrict__ Wa)
{
    extern __shared__ __align__(1024) unsigned char dsm[];
    const int tid  = threadIdx.x;
    const int bn   = blockIdx.x;
    const int bm   = blockIdx.y;
    const int wid  = tid >> 5, lane = tid & 31;
    const int wm   = wid & 1, wn = wid >> 1;
    const int m0   = bm * 128, n0 = bn * 128;
    const int K = L_DIM, NC = L_DIM / 32;   // 16
    const uint32_t sb = smem_u32(dsm);
    const int STG = 2 * TB32;               // A + B

    auto loadTile = [&](uint32_t dst, const void* p, int gr0, int k0) {
#pragma unroll
        for (int it = 0; it < 4; it++) {
            int q = tid + it * 128;
            int row = q >> 2;
            int c16 = q & 3;
            uint32_t off = (uint32_t)(row * 64) + (uint32_t)((c16 ^ ((row >> 1) & 3)) << 4);
            cp16(dst + off, (const char*)p + ((size_t)(gr0 + row) * K + k0 + c16 * 8) * 2);
        }
    };
    auto loadStage = [&](int s, int k0) {
        uint32_t st = sb + s * STG;
        loadTile(st,        A16, m0, k0);
        loadTile(st + TB32, B16, n0, k0);
        asm volatile("cp.async.commit_group;" ::: "memory");
    };

    const int aRow = wm * 64 + (lane & 15);
    const uint32_t aK  = ((lane >> 4) & 1) * 16;
    const uint32_t aSw = (uint32_t)((aRow >> 1) & 3) << 4;
    const int bRow = wn * 64 + (lane & 7) + (((lane >> 4) & 1) << 3);
    const uint32_t bK  = ((lane >> 3) & 1) * 16;
    const uint32_t bSw = (uint32_t)((bRow >> 1) & 3) << 4;

    float acc[4][8][4];
#pragma unroll
    for (int mi = 0; mi < 4; mi++)
#pragma unroll
        for (int ni = 0; ni < 8; ni++)
#pragma unroll
            for (int e = 0; e < 4; e++) acc[mi][ni][e] = 0.f;

    loadStage(0, 0);
    loadStage(1, 32);

    for (int i = 0; i < NC; i++) {
        if (i + 1 < NC) asm volatile("cp.async.wait_group 1;" ::: "memory");
        else            asm volatile("cp.async.wait_group 0;" ::: "memory");
        __syncthreads();
        if (i + 2 < NC) loadStage((i + 2) % 3, (i + 2) * 32);

        const uint32_t st = sb + (i % 3) * STG;
        const uint32_t sA = st, sB = st + TB32;

#pragma unroll
        for (int ks = 0; ks < 2; ks++) {
            uint32_t aa[4][4], bb[4][4];
            const uint32_t akc = (uint32_t)(ks * 32) + aK;
            const uint32_t bkc = (uint32_t)(ks * 32) + bK;
#pragma unroll
            for (int mi = 0; mi < 4; mi++) {
                uint32_t ro = (uint32_t)((aRow + mi * 16) * 64) + (akc ^ aSw);
                ldsm4(aa[mi], sA + ro);
            }
#pragma unroll
            for (int nj = 0; nj < 4; nj++) {
                uint32_t ro = (uint32_t)((bRow + nj * 16) * 64) + (bkc ^ bSw);
                ldsm4(bb[nj], sB + ro);
            }
#pragma unroll
            for (int mi = 0; mi < 4; mi++)
#pragma unroll
                for (int nj = 0; nj < 4; nj++) {
                    mma16816h(acc[mi][2 * nj],     aa[mi], &bb[nj][0]);
                    mma16816h(acc[mi][2 * nj + 1], aa[mi], &bb[nj][2]);
                }
        }
    }

    // fused gated-attention projection epilogue
    const int rBase = m0 + wm * 64 + (lane >> 2);
    const int cBase = n0 + wn * 64 + 2 * (lane & 3);
#pragma unroll
    for (int mi = 0; mi < 4; mi++) {
#pragma unroll
        for (int half = 0; half < 2; half++) {
            const int r = rBase + mi * 16 + half * 8;
            float s0 = 0.f, s1 = 0.f;
#pragma unroll
            for (int ni = 0; ni < 8; ni++) {
                const int c = cBase + ni * 8;
                float v0 = acc[mi][ni][2 * half]     + bias[c];
                float v1 = acc[mi][ni][2 * half + 1] + bias[c + 1];
                float gg = tanhf(v0) / (1.f + expf(-v1));
                const int gc = c >> 1;
                s0 = fmaf(gg, Wa[gc], s0);
                s1 = fmaf(gg, Wa[D_DIM + gc], s1);
            }
            s0 += __shfl_xor_sync(0xFFFFFFFFu, s0, 1);
            s0 += __shfl_xor_sync(0xFFFFFFFFu, s0, 2);
            s1 += __shfl_xor_sync(0xFFFFFFFFu, s1, 1);
            s1 += __shfl_xor_sync(0xFFFFFFFFu, s1, 2);
            if ((lane & 3) == 0) {
                atomicAdd(&g_A[2 * r],     s0);
                atomicAdd(&g_A[2 * r + 1], s1);
            }
        }
    }
}

// ---------------- finalize: +ba, raw_attention out, per-class max, histogram ----------------
__global__ void finalize_kernel(const float* __restrict__ ba, const int* __restrict__ labelPtr,
                                float* __restrict__ out_att)
{
    __shared__ unsigned sk0, sk1;
    if (threadIdx.x == 0) { sk0 = 0u; sk1 = 0u; }
    __syncthreads();
    int i = blockIdx.x * blockDim.x + threadIdx.x;
    int lab = labelPtr ? *labelPtr : 0;
    float a0 = g_A[2 * i] + ba[0];
    float a1 = g_A[2 * i + 1] + ba[1];
    g_A[2 * i] = a0; g_A[2 * i + 1] = a1;
    out_att[i] = a0;
    out_att[NROWS + i] = a1;
    atomicMax(&sk0, monoKey(a0));
    atomicMax(&sk1, monoKey(a1));
    float sel = lab ? a1 : a0;
    atomicAdd(&g_hist[monoKey(sel) >> 18], 1);
    __syncthreads();
    if (threadIdx.x == 0) {
        atomicMax(&g_maxkey[0], sk0);
        atomicMax(&g_maxkey[1], sk1);
    }
}

// ---------------- fused softmax-weighted bag accumulation (h fp16) ----------------
__global__ void bag_kernel()
{
    const int t = threadIdx.x;
    const int rowsPerBlock = NROWS / gridDim.x;
    const int r0 = blockIdx.x * rowsPerBlock;
    const float m0 = monoDecode(g_maxkey[0]);
    const float m1 = monoDecode(g_maxkey[1]);

    float a00 = 0.f, a01 = 0.f, a10 = 0.f, a11 = 0.f;
    float z0 = 0.f, z1 = 0.f;
    for (int r = r0; r < r0 + rowsPerBlock; r++) {
        float w0 = expf(g_A[2 * r]     - m0);
        float w1 = expf(g_A[2 * r + 1] - m1);
        const __half2* hp = (const __half2*)(g_h16 + (size_t)r * L_DIM);
        __half2 a2 = hp[t];
        float v0 = __low2float(a2);
        float v1 = __high2float(a2);
        a00 = fmaf(w0, v0, a00); a01 = fmaf(w0, v1, a01);
        a10 = fmaf(w1, v0, a10); a11 = fmaf(w1, v1, a11);
        if (t == 0) { z0 += w0; z1 += w1; }
    }
    atomicAdd(&g_bag[2 * t], a00);
    atomicAdd(&g_bag[2 * t + 1], a01);
    atomicAdd(&g_bag[L_DIM + 2 * t], a10);
    atomicAdd(&g_bag[L_DIM + 2 * t + 1], a11);
    if (t == 0) { atomicAdd(&g_Z[0], z0); atomicAdd(&g_Z[1], z1); }
}

// ---------------- top-k machinery ----------------
__global__ void scan_kernel()
{
    __shared__ int csum[256];
    int t = threadIdx.x;
    int s = 0;
    for (int b = t * 64; b < t * 64 + 64; b++) s += g_hist[b];
    csum[t] = s;
    __syncthreads();
    if (t == 0) {
        int cum = 0, binhi = 0;
        for (int c = 255; c >= 0; c--) {
            if (cum + csum[c] >= NI) {
                for (int b = c * 64 + 63; b >= c * 64; b--) {
                    cum += g_hist[b];
                    if (cum >= NI) { binhi = b; break; }
                }
                break;
            }
            cum += csum[c];
        }
        g_binhi = binhi;
        cum = 0; int binlo = 16383;
        for (int c = 0; c < 256; c++) {
            if (cum + csum[c] >= NI) {
                for (int b = c * 64; b < c * 64 + 64; b++) {
                    cum += g_hist[b];
                    if (cum >= NI) { binlo = b; break; }
                }
                break;
            }
            cum += csum[c];
        }
        g_binlo = binlo;
        g_nhi = 0; g_nlo = 0;
    }
}

__global__ void cand_kernel(const int* __restrict__ labelPtr)
{
    int lab = labelPtr ? *labelPtr : 0;
    int binhi = g_binhi, binlo = g_binlo;
    for (int i = blockIdx.x * blockDim.x + threadIdx.x; i < NROWS; i += gridDim.x * blockDim.x) {
        float v = g_A[2 * i + lab];
        unsigned key = monoKey(v) >> 18;
        if ((int)key >= binhi) {
            int p = atomicAdd(&g_nhi, 1);
            g_chv[p] = v; g_chi[p] = i;
        }
        if ((int)key <= binlo) {
            int p = atomicAdd(&g_nlo, 1);
            g_clv[p] = v; g_cli[p] = i;
        }
    }
}

__global__ void select_kernel()
{
    __shared__ float sv[256];
    __shared__ int   si[256];
    __shared__ int   sp[256];
    const int t = threadIdx.x;
    const float NEG_INF = __int_as_float(0xFF800000);
    const float POS_INF = __int_as_float(0x7F800000);
    int nhi = g_nhi, nlo = g_nlo;

    for (int it = 0; it < NI; it++) {
        float bv = NEG_INF; int bi = 0x7FFFFFFF; int bp = -1;
        for (int p = t; p < nhi; p += 256) {
            float v = g_chv[p]; int idx = g_chi[p];
            if (v > bv || (v == bv && idx < bi)) { bv = v; bi = idx; bp = p; }
        }
        sv[t] = bv; si[t] = bi; sp[t] = bp;
        __syncthreads();
        for (int s = 128; s; s >>= 1) {
            if (t < s) {
                if (sv[t + s] > sv[t] || (sv[t + s] == sv[t] && si[t + s] < si[t])) {
                    sv[t] = sv[t + s]; si[t] = si[t + s]; sp[t] = sp[t + s];
                }
            }
            __syncthreads();
        }
        if (t == 0) { g_inst[it] = si[0]; g_chv[sp[0]] = NEG_INF; }
        __syncthreads();
    }
    for (int it = 0; it < NI; it++) {
        float bv = POS_INF; int bi = 0x7FFFFFFF; int bp = -1;
        for (int p = t; p < nlo; p += 256) {
            float v = g_clv[p]; int idx = g_cli[p];
            if (v < bv || (v == bv && idx < bi)) { bv = v; bi = idx; bp = p; }
        }
        sv[t] = bv; si[t] = bi; sp[t] = bp;
        __syncthreads();
        for (int s = 128; s; s >>= 1) {
            if (t < s) {
                if (sv[t + s] < sv[t] || (sv[t + s] == sv[t] && si[t + s] < si[t])) {
                    sv[t] = sv[t + s]; si[t] = si[t + s]; sp[t] = sp[t + s];
                }
            }
            __syncthreads();
        }
        if (t == 0) { g_inst[NI + it] = si[0]; g_clv[sp[0]] = POS_INF; }
        __syncthreads();
    }
}

// ---------------- instance loss (h fp16) ----------------
__global__ void loss_kernel(const int* __restrict__ labelPtr,
                            const float* __restrict__ Winst, const float* __restrict__ binst,
                            float* __restrict__ out_loss)
{
    __shared__ float sl[4];
    int lab = labelPtr ? *labelPtr : 0;
    const float* W0 = Winst + ((size_t)lab * 2 + 0) * L_DIM;
    const float* W1 = Winst + ((size_t)lab * 2 + 1) * L_DIM;
    float b0 = binst[lab * 2], b1 = binst[lab * 2 + 1];

    int warp = threadIdx.x >> 5, lane = threadIdx.x & 31;
    float lsum = 0.f;
    for (int r = warp; r < 2 * NI; r += 4) {
        const __half* hp = g_h16 + (size_t)g_inst[r] * L_DIM;
        float s0 = 0.f, s1 = 0.f;
        for (int k = lane; k < L_DIM; k += 32) {
            float v = __half2float(hp[k]);
            s0 = fmaf(v, W0[k], s0);
            s1 = fmaf(v, W1[k], s1);
        }
#pragma unroll
        for (int o = 16; o; o >>= 1) {
            s0 += __shfl_xor_sync(0xFFFFFFFFu, s0, o);
            s1 += __shfl_xor_sync(0xFFFFFFFFu, s1, o);
        }
        if (lane == 0) {
            float l0 = s0 + b0, l1 = s1 + b1;
            int tgt = (r < NI) ? 1 : 0;
            float u0 = l0 + ((tgt != 0) ? 1.f : 0.f);
            float u1 = l1 + ((tgt != 1) ? 1.f : 0.f);
            float m = fmaxf(u0, u1);
            float lse = m + logf(expf(u0 - m) + expf(u1 - m));
            float sy = (tgt == 0) ? l0 : l1;
            lsum += lse - sy;
        }
    }
    if (lane == 0) sl[warp] = lsum;
    __syncthreads();
    if (threadIdx.x == 0)
        *out_loss = (sl[0] + sl[1] + sl[2] + sl[3]) * (1.f / (2 * NI));
}

// ---------------- bag logits + softmax ----------------
__global__ void final_kernel(const float* __restrict__ Wbag, const float* __restrict__ bbag,
                             float* __restrict__ out)
{
    __shared__ float lg[2];
    int warp = threadIdx.x >> 5, lane = threadIdx.x & 31;
    if (warp < 2) {
        float s = 0.f;
        for (int k = lane; k < L_DIM; k += 32)
            s = fmaf(g_bag[warp * L_DIM + k], Wbag[warp * L_DIM + k], s);
#pragma unroll
        for (int o = 16; o; o >>= 1) s += __shfl_xor_sync(0xFFFFFFFFu, s, o);
        if (lane == 0) lg[warp] = s / g_Z[warp] + bbag[warp];
    }
    __syncthreads();
    if (threadIdx.x == 0) {
        float l0 = lg[0], l1 = lg[1];
        out[0] = l0; out[1] = l1;
        float m = fmaxf(l0, l1);
        float e0 = expf(l0 - m), e1 = expf(l1 - m);
        float s = e0 + e1;
        out[2] = e0 / s; out[3] = e1 / s;
    }
}

// ---------------- launch ----------------
extern "C" void kernel_launch(void* const* d_in, const int* in_sizes, int n_in,
                              void* d_out, int out_size)
{
    const int off = (n_in >= 14) ? 1 : 0;
    const float* x     = (const float*)d_in[0];
    const int*   label = (n_in >= 14) ? (const int*)d_in[1] : nullptr;
    const float* Wc    = (const float*)d_in[1 + off];
    const float* bc    = (const float*)d_in[2 + off];
    const float* Wv    = (const float*)d_in[3 + off];
    const float* bv    = (const float*)d_in[4 + off];
    const float* Wu    = (const float*)d_in[5 + off];
    const float* bu    = (const float*)d_in[6 + off];
    const float* Wa    = (const float*)d_in[7 + off];
    const float* ba    = (const float*)d_in[8 + off];
    const float* Winst = (const float*)d_in[9 + off];
    const float* binst = (const float*)d_in[10 + off];
    const float* Wbag  = (const float*)d_in[11 + off];
    const float* bbag  = (const float*)d_in[12 + off];
    float* out = (float*)d_out;

    void* p;
    cudaGetSymbolAddress(&p, g_h16);  __half* h16 = (__half*)p;
    cudaGetSymbolAddress(&p, g_wc16); __half* wc16 = (__half*)p;
    cudaGetSymbolAddress(&p, g_wt16); __half* wt16 = (__half*)p;
    cudaGetSymbolAddress(&p, g_bcat); float* bcat = (float*)p;

    cudaFuncSetAttribute(gemm1_fused, cudaFuncAttributeMaxDynamicSharedMemorySize, G1_SMEM);
    cudaFuncSetAttribute(gemm2_hmma,  cudaFuncAttributeMaxDynamicSharedMemorySize, G2_SMEM);

    // launches #1..#3 (gemm1 stays launch #4 for ncu)
    init_kernel<<<1024, 256>>>();
    cvtw_kernel<<<256, 256>>>((const float4*)Wc, (__half2*)wc16, (L_DIM * E_DIM) / 4);
    cat_kernel<<<(2 * D_DIM * L_DIM + 255) / 256, 256>>>(Wv, Wu, bv, bu, wt16, bcat);

    // GEMM1 (launch #4): h = relu(x @ Wc^T + bc) -> fp16 (R13 shape)
    gemm1_fused<<<dim3(4, NROWS / 128), 128, G1_SMEM>>>(x, wc16, bc, h16);

    // GEMM2+3 + attention fused (single fp16 product)
    gemm2_hmma<<<dim3(4, NROWS / 128), 128, G2_SMEM>>>(h16, wt16, bcat, Wa);

    finalize_kernel<<<NROWS / 256, 256>>>(ba, label, out + 4);
    scan_kernel<<<1, 256>>>();
    cand_kernel<<<NROWS / 256, 256>>>(label);
    select_kernel<<<1, 256>>>();
    loss_kernel<<<1, 128>>>(label, Winst, binst, out + 4 + 2 * NROWS);
    bag_kernel<<<512, 256>>>();
    final_kernel<<<1, 64>>>(Wbag, bbag, out);
}

// round 16
// speedup vs baseline: 1.2510x; 1.0436x over previous
#include <cuda_runtime.h>
#include <cuda_bf16.h>
#include <cuda_fp16.h>
#include <math.h>
#include <stdint.h>

#define NROWS 131072
#define E_DIM 1024
#define L_DIM 512
#define D_DIM 256
#define NI    50

// ---------------- device scratch (allocation-free rule) ----------------
__device__ __half g_h16[(size_t)NROWS * L_DIM];   // h as single fp16
__device__ __half g_wc16[L_DIM * E_DIM];          // Wc single fp16
__device__ __half g_wt16[2 * D_DIM * L_DIM];      // Wcat single fp16
__device__ float g_bcat[2 * D_DIM];
__device__ float g_A[(size_t)NROWS * 2];
__device__ int      g_hist[16384];
__device__ unsigned g_maxkey[2];
__device__ float    g_Z[2];
__device__ float    g_bag[2 * L_DIM];
__device__ int      g_binhi, g_binlo;
__device__ int      g_nhi, g_nlo;
__device__ float g_chv[NROWS]; __device__ int g_chi[NROWS];
__device__ float g_clv[NROWS]; __device__ int g_cli[NROWS];
__device__ int   g_inst[2 * NI];

// ---------------- PTX helpers ----------------
__device__ __forceinline__ uint32_t smem_u32(const void* p) {
    uint32_t a;
    asm("{ .reg .u64 t; cvta.to.shared.u64 t, %1; cvt.u32.u64 %0, t; }" : "=r"(a) : "l"(p));
    return a;
}
__device__ __forceinline__ void cp16(uint32_t s, const void* g) {
    asm volatile("cp.async.cg.shared.global [%0], [%1], 16;" :: "r"(s), "l"(g));
}
__device__ __forceinline__ void ldsm4(uint32_t* r, uint32_t addr) {
    asm volatile("ldmatrix.sync.aligned.m8n8.x4.shared.b16 {%0,%1,%2,%3}, [%4];"
                 : "=r"(r[0]), "=r"(r[1]), "=r"(r[2]), "=r"(r[3]) : "r"(addr));
}
__device__ __forceinline__ void mma16816h(float* c, const uint32_t* a, const uint32_t* b) {
    asm volatile(
        "mma.sync.aligned.m16n8k16.row.col.f32.f16.f16.f32 "
        "{%0,%1,%2,%3}, {%4,%5,%6,%7}, {%8,%9}, {%0,%1,%2,%3};"
        : "+f"(c[0]), "+f"(c[1]), "+f"(c[2]), "+f"(c[3])
        : "r"(a[0]), "r"(a[1]), "r"(a[2]), "r"(a[3]), "r"(b[0]), "r"(b[1]));
}

// monotone float <-> uint key
__device__ __forceinline__ unsigned monoKey(float f) {
    unsigned u = __float_as_uint(f);
    return (u & 0x80000000u) ? ~u : (u | 0x80000000u);
}
__device__ __forceinline__ float monoDecode(unsigned k) {
    unsigned u = (k & 0x80000000u) ? (k & 0x7FFFFFFFu) : ~k;
    return __uint_as_float(u);
}

__device__ __forceinline__ uint32_t packh2(float a, float b) {
    __half2 t = __halves2half2(__float2half(a), __float2half(b));
    return *(uint32_t*)&t;
}

// ---------------- merged prep: init + Wc fp16 convert + Wcat build ----------------
__global__ void prep_kernel(const float4* __restrict__ Wc, __half2* __restrict__ wc16,
                            const float* __restrict__ Wv, const float* __restrict__ Wu,
                            const float* __restrict__ bv, const float* __restrict__ bu,
                            __half* __restrict__ wt16, float* __restrict__ bcat)
{
    int i = blockIdx.x * blockDim.x + threadIdx.x;   // 262144 threads
    // init
    if (i < 2 * NROWS) g_A[i] = 0.f;
    if (i < 16384) g_hist[i] = 0;
    if (i < 2 * L_DIM) g_bag[i] = 0.f;
    if (i < 2) { g_Z[i] = 0.f; g_maxkey[i] = 0u; }
    if (i == 0) { g_nhi = 0; g_nlo = 0; }
    // Wc fp32 -> fp16 (float4 granularity, n4 = 131072)
    if (i < (L_DIM * E_DIM) / 4) {
        float4 v = Wc[i];
        wc16[2 * i]     = __halves2half2(__float2half(v.x), __float2half(v.y));
        wc16[2 * i + 1] = __halves2half2(__float2half(v.z), __float2half(v.w));
    }
    // Wcat interleave (262144 elements)
    if (i < 2 * D_DIM * L_DIM) {
        int row = i >> 9, k = i & 511;
        int j = row >> 1, e = row & 1;
        float v = e ? Wu[j * L_DIM + k] : Wv[j * L_DIM + k];
        wt16[i] = __float2half(v);
    }
    if (i < 2 * D_DIM) {
        int j = i >> 1, e = i & 1;
        bcat[i] = e ? bu[j] : bv[j];
    }
}

// ===== GEMM config (R13 shape): 128 threads, warp grid 2x2, warp tile 64x64, BK=32 =====
#define TB32 8192
#define G1_SMEM (2 * TB32 + 3 * TB32)     // conv x 2x8KB + B 3x8KB = 40KB
#define G2_SMEM (3 * 2 * TB32)            // 3 stages x (A, B) = 48KB

__global__ __launch_bounds__(128, 2)
void gemm1_fused(const float* __restrict__ X,
                 const __half* __restrict__ B16,
                 const float* __restrict__ bias,
                 __half* __restrict__ OutH)
{
    extern __shared__ __align__(1024) unsigned char dsm[];
    const int tid  = threadIdx.x;
    const int bn   = blockIdx.x;
    const int bm   = blockIdx.y;
    const int wid  = tid >> 5, lane = tid & 31;
    const int wm   = wid & 1, wn = wid >> 1;
    const int m0   = bm * 128, n0 = bn * 128;
    const int K = E_DIM, NC = E_DIM / 32;          // 32
    const uint32_t sb = smem_u32(dsm);
    const uint32_t convB = sb;
    const uint32_t bBase = sb + 2 * TB32;

    auto loadB = [&](int s, int k0) {
        uint32_t dst = bBase + s * TB32;
#pragma unroll
        for (int it = 0; it < 4; it++) {
            int q = tid + it * 128;
            int row = q >> 2;
            int c16 = q & 3;
            uint32_t off = (uint32_t)(row * 64) + (uint32_t)((c16 ^ ((row >> 1) & 3)) << 4);
            cp16(dst + off, (const char*)B16 + ((size_t)(n0 + row) * K + k0 + c16 * 8) * 2);
        }
        asm volatile("cp.async.commit_group;" ::: "memory");
    };

    float4 xr[8];
    const int xrow = tid >> 1;
    const int xseg2 = (tid & 1) * 2;
    auto ldgX = [&](int k0) {
        const float* src = X + (size_t)(m0 + xrow) * K + k0 + xseg2 * 8;
#pragma unroll
        for (int j = 0; j < 4; j++) xr[2 * j]     = *(const float4*)(src + j * 4);
        const float* src2 = X + (size_t)(m0 + 64 + xrow) * K + k0 + xseg2 * 8;
#pragma unroll
        for (int j = 0; j < 4; j++) xr[2 * j + 1] = *(const float4*)(src2 + j * 4);
    };
    auto stsX = [&](int buf) {
        unsigned char* hp = dsm + buf * TB32;
#pragma unroll
        for (int half = 0; half < 2; half++) {
            int row = xrow + half * 64;
            const uint32_t sw = (uint32_t)((row >> 1) & 3);
#pragma unroll
            for (int s2 = 0; s2 < 2; s2++) {
                int seg = xseg2 + s2;
                float4 a = xr[(2 * s2) * 2 + half];
                float4 b = xr[(2 * s2 + 1) * 2 + half];
                uint32_t off = (uint32_t)(row * 64) + (uint32_t)(((uint32_t)seg ^ sw) << 4);
                uint4 hv;
                hv.x = packh2(a.x, a.y); hv.y = packh2(a.z, a.w);
                hv.z = packh2(b.x, b.y); hv.w = packh2(b.z, b.w);
                *(uint4*)(hp + off) = hv;
            }
        }
    };

    const int aRow = wm * 64 + (lane & 15);
    const uint32_t aK  = ((lane >> 4) & 1) * 16;
    const uint32_t aSw = (uint32_t)((aRow >> 1) & 3) << 4;
    const int bRow = wn * 64 + (lane & 7) + (((lane >> 4) & 1) << 3);
    const uint32_t bK  = ((lane >> 3) & 1) * 16;
    const uint32_t bSw = (uint32_t)((bRow >> 1) & 3) << 4;

    float acc[4][8][4];
#pragma unroll
    for (int mi = 0; mi < 4; mi++)
#pragma unroll
        for (int ni = 0; ni < 8; ni++)
#pragma unroll
            for (int e = 0; e < 4; e++) acc[mi][ni][e] = 0.f;

    loadB(0, 0);
    loadB(1, 32);
    ldgX(0);
    stsX(0);
    ldgX(32);

    for (int i = 0; i < NC; i++) {
        if (i + 1 < NC) asm volatile("cp.async.wait_group 1;" ::: "memory");
        else            asm volatile("cp.async.wait_group 0;" ::: "memory");
        __syncthreads();
        if (i + 2 < NC) loadB((i + 2) % 3, (i + 2) * 32);
        if (i + 1 < NC) stsX((i + 1) & 1);
        if (i + 2 < NC) ldgX((i + 2) * 32);

        const uint32_t sA = convB + (i & 1) * TB32;
        const uint32_t sB = bBase + (i % 3) * TB32;

#pragma unroll
        for (int ks = 0; ks < 2; ks++) {
            uint32_t aa[4][4], bb[4][4];
            const uint32_t akc = (uint32_t)(ks * 32) + aK;
            const uint32_t bkc = (uint32_t)(ks * 32) + bK;
#pragma unroll
            for (int mi = 0; mi < 4; mi++) {
                uint32_t ro = (uint32_t)((aRow + mi * 16) * 64) + (akc ^ aSw);
                ldsm4(aa[mi], sA + ro);
            }
#pragma unroll
            for (int nj = 0; nj < 4; nj++) {
                uint32_t ro = (uint32_t)((bRow + nj * 16) * 64) + (bkc ^ bSw);
                ldsm4(bb[nj], sB + ro);
            }
#pragma unroll
            for (int mi = 0; mi < 4; mi++)
#pragma unroll
                for (int nj = 0; nj < 4; nj++) {
                    mma16816h(acc[mi][2 * nj],     aa[mi], &bb[nj][0]);
                    mma16816h(acc[mi][2 * nj + 1], aa[mi], &bb[nj][2]);
                }
        }
    }

    const int rBase = m0 + wm * 64 + (lane >> 2);
    const int cBase = n0 + wn * 64 + 2 * (lane & 3);
#pragma unroll
    for (int mi = 0; mi < 4; mi++) {
#pragma unroll
        for (int ni = 0; ni < 8; ni++) {
            const int c = cBase + ni * 8;
            const float b0 = bias[c], b1 = bias[c + 1];
#pragma unroll
            for (int half = 0; half < 2; half++) {
                const int r = rBase + mi * 16 + half * 8;
                float v0 = fmaxf(acc[mi][ni][2 * half]     + b0, 0.f);
                float v1 = fmaxf(acc[mi][ni][2 * half + 1] + b1, 0.f);
                size_t o = ((size_t)r * 512 + c) >> 1;
                ((__half2*)OutH)[o] = __halves2half2(__float2half(v0), __float2half(v1));
            }
        }
    }
}

// GEMM2: A = h fp16, B = Wcat fp16, single product. Sigmoid via tanh (no expf).
__global__ __launch_bounds__(128, 2)
void gemm2_hmma(const __half* __restrict__ A16,
                const __half* __restrict__ B16,
                const float* __restrict__ bias, const float* __restrict__ Wa)
{
    extern __shared__ __align__(1024) unsigned char dsm[];
    const int tid  = threadIdx.x;
    const int bn   = blockIdx.x;
    const int bm   = blockIdx.y;
    const int wid  = tid >> 5, lane = tid & 31;
    const int wm   = wid & 1, wn = wid >> 1;
    const int m0   = bm * 128, n0 = bn * 128;
    const int K = L_DIM, NC = L_DIM / 32;   // 16
    const uint32_t sb = smem_u32(dsm);
    const int STG = 2 * TB32;

    auto loadTile = [&](uint32_t dst, const void* p, int gr0, int k0) {
#pragma unroll
        for (int it = 0; it < 4; it++) {
            int q = tid + it * 128;
            int row = q >> 2;
            int c16 = q & 3;
            uint32_t off = (uint32_t)(row * 64) + (uint32_t)((c16 ^ ((row >> 1) & 3)) << 4);
            cp16(dst + off, (const char*)p + ((size_t)(gr0 + row) * K + k0 + c16 * 8) * 2);
        }
    };
    auto loadStage = [&](int s, int k0) {
        uint32_t st = sb + s * STG;
        loadTile(st,        A16, m0, k0);
        loadTile(st + TB32, B16, n0, k0);
        asm volatile("cp.async.commit_group;" ::: "memory");
    };

    const int aRow = wm * 64 + (lane & 15);
    const uint32_t aK  = ((lane >> 4) & 1) * 16;
    const uint32_t aSw = (uint32_t)((aRow >> 1) & 3) << 4;
    const int bRow = wn * 64 + (lane & 7) + (((lane >> 4) & 1) << 3);
    const uint32_t bK  = ((lane >> 3) & 1) * 16;
    const uint32_t bSw = (uint32_t)((bRow >> 1) & 3) << 4;

    float acc[4][8][4];
#pragma unroll
    for (int mi = 0; mi < 4; mi++)
#pragma unroll
        for (int ni = 0; ni < 8; ni++)
#pragma unroll
            for (int e = 0; e < 4; e++) acc[mi][ni][e] = 0.f;

    loadStage(0, 0);
    loadStage(1, 32);

    for (int i = 0; i < NC; i++) {
        if (i + 1 < NC) asm volatile("cp.async.wait_group 1;" ::: "memory");
        else            asm volatile("cp.async.wait_group 0;" ::: "memory");
        __syncthreads();
        if (i + 2 < NC) loadStage((i + 2) % 3, (i + 2) * 32);

        const uint32_t st = sb + (i % 3) * STG;
        const uint32_t sA = st, sB = st + TB32;

#pragma unroll
        for (int ks = 0; ks < 2; ks++) {
            uint32_t aa[4][4], bb[4][4];
            const uint32_t akc = (uint32_t)(ks * 32) + aK;
            const uint32_t bkc = (uint32_t)(ks * 32) + bK;
#pragma unroll
            for (int mi = 0; mi < 4; mi++) {
                uint32_t ro = (uint32_t)((aRow + mi * 16) * 64) + (akc ^ aSw);
                ldsm4(aa[mi], sA + ro);
            }
#pragma unroll
            for (int nj = 0; nj < 4; nj++) {
                uint32_t ro = (uint32_t)((bRow + nj * 16) * 64) + (bkc ^ bSw);
                ldsm4(bb[nj], sB + ro);
            }
#pragma unroll
            for (int mi = 0; mi < 4; mi++)
#pragma unroll
                for (int nj = 0; nj < 4; nj++) {
                    mma16816h(acc[mi][2 * nj],     aa[mi], &bb[nj][0]);
                    mma16816h(acc[mi][2 * nj + 1], aa[mi], &bb[nj][2]);
                }
        }
    }

    // fused gated-attention projection epilogue (sigmoid via tanh identity)
    const int rBase = m0 + wm * 64 + (lane >> 2);
    const int cBase = n0 + wn * 64 + 2 * (lane & 3);
#pragma unroll
    for (int mi = 0; mi < 4; mi++) {
#pragma unroll
        for (int half = 0; half < 2; half++) {
            const int r = rBase + mi * 16 + half * 8;
            float s0 = 0.f, s1 = 0.f;
#pragma unroll
            for (int ni = 0; ni < 8; ni++) {
                const int c = cBase + ni * 8;
                float v0 = acc[mi][ni][2 * half]     + bias[c];
                float v1 = acc[mi][ni][2 * half + 1] + bias[c + 1];
                float gg = tanhf(v0) * (0.5f + 0.5f * tanhf(0.5f * v1));
                const int gc = c >> 1;
                s0 = fmaf(gg, Wa[gc], s0);
                s1 = fmaf(gg, Wa[D_DIM + gc], s1);
            }
            s0 += __shfl_xor_sync(0xFFFFFFFFu, s0, 1);
            s0 += __shfl_xor_sync(0xFFFFFFFFu, s0, 2);
            s1 += __shfl_xor_sync(0xFFFFFFFFu, s1, 1);
            s1 += __shfl_xor_sync(0xFFFFFFFFu, s1, 2);
            if ((lane & 3) == 0) {
                atomicAdd(&g_A[2 * r],     s0);
                atomicAdd(&g_A[2 * r + 1], s1);
            }
        }
    }
}

// ---------------- finalize: +ba, raw_attention out, per-class max, histogram ----------------
__global__ void finalize_kernel(const float* __restrict__ ba, const int* __restrict__ labelPtr,
                                float* __restrict__ out_att)
{
    __shared__ unsigned sk0, sk1;
    if (threadIdx.x == 0) { sk0 = 0u; sk1 = 0u; }
    __syncthreads();
    int i = blockIdx.x * blockDim.x + threadIdx.x;
    int lab = labelPtr ? *labelPtr : 0;
    float a0 = g_A[2 * i] + ba[0];
    float a1 = g_A[2 * i + 1] + ba[1];
    g_A[2 * i] = a0; g_A[2 * i + 1] = a1;
    out_att[i] = a0;
    out_att[NROWS + i] = a1;
    atomicMax(&sk0, monoKey(a0));
    atomicMax(&sk1, monoKey(a1));
    float sel = lab ? a1 : a0;
    atomicAdd(&g_hist[monoKey(sel) >> 18], 1);
    __syncthreads();
    if (threadIdx.x == 0) {
        atomicMax(&g_maxkey[0], sk0);
        atomicMax(&g_maxkey[1], sk1);
    }
}

// ---------------- vectorized softmax-weighted bag accumulation ----------------
__global__ void bag_kernel()
{
    const int t = threadIdx.x;               // 256 threads
    const int sub  = t >> 6;                 // 0..3 (row lane)
    const int cseg = t & 63;                 // col segment: 8 halves
    const int r0 = blockIdx.x * 256;
    const float m0 = monoDecode(g_maxkey[0]);
    const float m1 = monoDecode(g_maxkey[1]);

    float a0[8], a1[8];
#pragma unroll
    for (int j = 0; j < 8; j++) { a0[j] = 0.f; a1[j] = 0.f; }
    float z0 = 0.f, z1 = 0.f;

    for (int r = r0 + sub; r < r0 + 256; r += 4) {
        float w0 = expf(g_A[2 * r]     - m0);
        float w1 = expf(g_A[2 * r + 1] - m1);
        uint4 v = *(const uint4*)(g_h16 + (size_t)r * 512 + cseg * 8);
        const __half2* hv = (const __half2*)&v;
#pragma unroll
        for (int j = 0; j < 4; j++) {
            float lo = __low2float(hv[j]), hi = __high2float(hv[j]);
            a0[2 * j]     = fmaf(w0, lo, a0[2 * j]);
            a0[2 * j + 1] = fmaf(w0, hi, a0[2 * j + 1]);
            a1[2 * j]     = fmaf(w1, lo, a1[2 * j]);
            a1[2 * j + 1] = fmaf(w1, hi, a1[2 * j + 1]);
        }
        if (cseg == 0) { z0 += w0; z1 += w1; }
    }

    __shared__ float sm[256][17];
    __shared__ float szm[8];
#pragma unroll
    for (int j = 0; j < 8; j++) { sm[t][j] = a0[j]; sm[t][8 + j] = a1[j]; }
    if (cseg == 0) { szm[sub] = z0; szm[4 + sub] = z1; }
    __syncthreads();
    if (sub == 0) {
#pragma unroll
        for (int j = 0; j < 8; j++) {
            float s0 = sm[cseg][j] + sm[cseg + 64][j] + sm[cseg + 128][j] + sm[cseg + 192][j];
            float s1 = sm[cseg][8 + j] + sm[cseg + 64][8 + j] + sm[cseg + 128][8 + j] + sm[cseg + 192][8 + j];
            atomicAdd(&g_bag[cseg * 8 + j], s0);
            atomicAdd(&g_bag[L_DIM + cseg * 8 + j], s1);
        }
    }
    if (t == 0) {
        atomicAdd(&g_Z[0], szm[0] + szm[1] + szm[2] + szm[3]);
        atomicAdd(&g_Z[1], szm[4] + szm[5] + szm[6] + szm[7]);
    }
}

// ---------------- top-k machinery ----------------
__global__ void scan_kernel()
{
    __shared__ int csum[256];
    int t = threadIdx.x;
    int s = 0;
    for (int b = t * 64; b < t * 64 + 64; b++) s += g_hist[b];
    csum[t] = s;
    __syncthreads();
    if (t == 0) {
        int cum = 0, binhi = 0;
        for (int c = 255; c >= 0; c--) {
            if (cum + csum[c] >= NI) {
                for (int b = c * 64 + 63; b >= c * 64; b--) {
                    cum += g_hist[b];
                    if (cum >= NI) { binhi = b; break; }
                }
                break;
            }
            cum += csum[c];
        }
        g_binhi = binhi;
        cum = 0; int binlo = 16383;
        for (int c = 0; c < 256; c++) {
            if (cum + csum[c] >= NI) {
                for (int b = c * 64; b < c * 64 + 64; b++) {
                    cum += g_hist[b];
                    if (cum >= NI) { binlo = b; break; }
                }
                break;
            }
            cum += csum[c];
        }
        g_binlo = binlo;
        g_nhi = 0; g_nlo = 0;
    }
}

__global__ void cand_kernel(const int* __restrict__ labelPtr)
{
    int lab = labelPtr ? *labelPtr : 0;
    int binhi = g_binhi, binlo = g_binlo;
    for (int i = blockIdx.x * blockDim.x + threadIdx.x; i < NROWS; i += gridDim.x * blockDim.x) {
        float v = g_A[2 * i + lab];
        unsigned key = monoKey(v) >> 18;
        if ((int)key >= binhi) {
            int p = atomicAdd(&g_nhi, 1);
            g_chv[p] = v; g_chi[p] = i;
        }
        if ((int)key <= binlo) {
            int p = atomicAdd(&g_nlo, 1);
            g_clv[p] = v; g_cli[p] = i;
        }
    }
}

__global__ void select_kernel()
{
    __shared__ float sv[256];
    __shared__ int   si[256];
    __shared__ int   sp[256];
    const int t = threadIdx.x;
    const float NEG_INF = __int_as_float(0xFF800000);
    const float POS_INF = __int_as_float(0x7F800000);
    int nhi = g_nhi, nlo = g_nlo;

    for (int it = 0; it < NI; it++) {
        float bv = NEG_INF; int bi = 0x7FFFFFFF; int bp = -1;
        for (int p = t; p < nhi; p += 256) {
            float v = g_chv[p]; int idx = g_chi[p];
            if (v > bv || (v == bv && idx < bi)) { bv = v; bi = idx; bp = p; }
        }
        sv[t] = bv; si[t] = bi; sp[t] = bp;
        __syncthreads();
        for (int s = 128; s; s >>= 1) {
            if (t < s) {
                if (sv[t + s] > sv[t] || (sv[t + s] == sv[t] && si[t + s] < si[t])) {
                    sv[t] = sv[t + s]; si[t] = si[t + s]; sp[t] = sp[t + s];
                }
            }
            __syncthreads();
        }
        if (t == 0) { g_inst[it] = si[0]; g_chv[sp[0]] = NEG_INF; }
        __syncthreads();
    }
    for (int it = 0; it < NI; it++) {
        float bv = POS_INF; int bi = 0x7FFFFFFF; int bp = -1;
        for (int p = t; p < nlo; p += 256) {
            float v = g_clv[p]; int idx = g_cli[p];
            if (v < bv || (v == bv && idx < bi)) { bv = v; bi = idx; bp = p; }
        }
        sv[t] = bv; si[t] = bi; sp[t] = bp;
        __syncthreads();
        for (int s = 128; s; s >>= 1) {
            if (t < s) {
                if (sv[t + s] < sv[t] || (sv[t + s] == sv[t] && si[t + s] < si[t])) {
                    sv[t] = sv[t + s]; si[t] = si[t + s]; sp[t] = sp[t + s];
                }
            }
            __syncthreads();
        }
        if (t == 0) { g_inst[NI + it] = si[0]; g_clv[sp[0]] = POS_INF; }
        __syncthreads();
    }
}

// ---------------- instance loss (h fp16) ----------------
__global__ void loss_kernel(const int* __restrict__ labelPtr,
                            const float* __restrict__ Winst, const float* __restrict__ binst,
                            float* __restrict__ out_loss)
{
    __shared__ float sl[4];
    int lab = labelPtr ? *labelPtr : 0;
    const float* W0 = Winst + ((size_t)lab * 2 + 0) * L_DIM;
    const float* W1 = Winst + ((size_t)lab * 2 + 1) * L_DIM;
    float b0 = binst[lab * 2], b1 = binst[lab * 2 + 1];

    int warp = threadIdx.x >> 5, lane = threadIdx.x & 31;
    float lsum = 0.f;
    for (int r = warp; r < 2 * NI; r += 4) {
        const __half* hp = g_h16 + (size_t)g_inst[r] * L_DIM;
        float s0 = 0.f, s1 = 0.f;
        for (int k = lane; k < L_DIM; k += 32) {
            float v = __half2float(hp[k]);
            s0 = fmaf(v, W0[k], s0);
            s1 = fmaf(v, W1[k], s1);
        }
#pragma unroll
        for (int o = 16; o; o >>= 1) {
            s0 += __shfl_xor_sync(0xFFFFFFFFu, s0, o);
            s1 += __shfl_xor_sync(0xFFFFFFFFu, s1, o);
        }
        if (lane == 0) {
            float l0 = s0 + b0, l1 = s1 + b1;
            int tgt = (r < NI) ? 1 : 0;
            float u0 = l0 + ((tgt != 0) ? 1.f : 0.f);
            float u1 = l1 + ((tgt != 1) ? 1.f : 0.f);
            float m = fmaxf(u0, u1);
            float lse = m + logf(expf(u0 - m) + expf(u1 - m));
            float sy = (tgt == 0) ? l0 : l1;
            lsum += lse - sy;
        }
    }
    if (lane == 0) sl[warp] = lsum;
    __syncthreads();
    if (threadIdx.x == 0)
        *out_loss = (sl[0] + sl[1] + sl[2] + sl[3]) * (1.f / (2 * NI));
}

// ---------------- bag logits + softmax ----------------
__global__ void final_kernel(const float* __restrict__ Wbag, const float* __restrict__ bbag,
                             float* __restrict__ out)
{
    __shared__ float lg[2];
    int warp = threadIdx.x >> 5, lane = threadIdx.x & 31;
    if (warp < 2) {
        float s = 0.f;
        for (int k = lane; k < L_DIM; k += 32)
            s = fmaf(g_bag[warp * L_DIM + k], Wbag[warp * L_DIM + k], s);
#pragma unroll
        for (int o = 16; o; o >>= 1) s += __shfl_xor_sync(0xFFFFFFFFu, s, o);
        if (lane == 0) lg[warp] = s / g_Z[warp] + bbag[warp];
    }
    __syncthreads();
    if (threadIdx.x == 0) {
        float l0 = lg[0], l1 = lg[1];
        out[0] = l0; out[1] = l1;
        float m = fmaxf(l0, l1);
        float e0 = expf(l0 - m), e1 = expf(l1 - m);
        float s = e0 + e1;
        out[2] = e0 / s; out[3] = e1 / s;
    }
}

// ---------------- launch ----------------
extern "C" void kernel_launch(void* const* d_in, const int* in_sizes, int n_in,
                              void* d_out, int out_size)
{
    const int off = (n_in >= 14) ? 1 : 0;
    const float* x     = (const float*)d_in[0];
    const int*   label = (n_in >= 14) ? (const int*)d_in[1] : nullptr;
    const float* Wc    = (const float*)d_in[1 + off];
    const float* bc    = (const float*)d_in[2 + off];
    const float* Wv    = (const float*)d_in[3 + off];
    const float* bv    = (const float*)d_in[4 + off];
    const float* Wu    = (const float*)d_in[5 + off];
    const float* bu    = (const float*)d_in[6 + off];
    const float* Wa    = (const float*)d_in[7 + off];
    const float* ba    = (const float*)d_in[8 + off];
    const float* Winst = (const float*)d_in[9 + off];
    const float* binst = (const float*)d_in[10 + off];
    const float* Wbag  = (const float*)d_in[11 + off];
    const float* bbag  = (const float*)d_in[12 + off];
    float* out = (float*)d_out;

    void* p;
    cudaGetSymbolAddress(&p, g_h16);  __half* h16 = (__half*)p;
    cudaGetSymbolAddress(&p, g_wc16); __half* wc16 = (__half*)p;
    cudaGetSymbolAddress(&p, g_wt16); __half* wt16 = (__half*)p;
    cudaGetSymbolAddress(&p, g_bcat); float* bcat = (float*)p;

    cudaFuncSetAttribute(gemm1_fused, cudaFuncAttributeMaxDynamicSharedMemorySize, G1_SMEM);
    cudaFuncSetAttribute(gemm2_hmma,  cudaFuncAttributeMaxDynamicSharedMemorySize, G2_SMEM);

    // merged prep (1 launch)
    prep_kernel<<<1024, 256>>>((const float4*)Wc, (__half2*)wc16, Wv, Wu, bv, bu, wt16, bcat);

    // GEMM1: h = relu(x @ Wc^T + bc) -> fp16
    gemm1_fused<<<dim3(4, NROWS / 128), 128, G1_SMEM>>>(x, wc16, bc, h16);

    // GEMM2+3 + attention fused (single fp16 product, MUFU-light epilogue)
    gemm2_hmma<<<dim3(4, NROWS / 128), 128, G2_SMEM>>>(h16, wt16, bcat, Wa);

    finalize_kernel<<<NROWS / 256, 256>>>(ba, label, out + 4);
    scan_kernel<<<1, 256>>>();
    cand_kernel<<<NROWS / 256, 256>>>(label);
    select_kernel<<<1, 256>>>();
    loss_kernel<<<1, 128>>>(label, Winst, binst, out + 4 + 2 * NROWS);
    bag_kernel<<<512, 256>>>();
    final_kernel<<<1, 64>>>(Wbag, bbag, out);
}

// round 17
// speedup vs baseline: 1.3390x; 1.0703x over previous
#include <cuda_runtime.h>
#include <cuda_bf16.h>
#include <cuda_fp16.h>
#include <math.h>
#include <stdint.h>

#define NROWS 131072
#define E_DIM 1024
#define L_DIM 512
#define D_DIM 256
#define NI    50

// ---------------- device scratch (allocation-free rule) ----------------
__device__ __half g_h16[(size_t)NROWS * L_DIM];   // h as single fp16
__device__ __half g_wc16[L_DIM * E_DIM];          // Wc single fp16
__device__ __half g_wt16[2 * D_DIM * L_DIM];      // Wcat single fp16
__device__ float g_bcat[2 * D_DIM];
__device__ float g_A[(size_t)NROWS * 2];
__device__ int      g_hist[16384];
__device__ unsigned g_maxkey[2];
__device__ float    g_Z[2];
__device__ float    g_bag[2 * L_DIM];
__device__ int      g_binhi, g_binlo;
__device__ int      g_nhi, g_nlo;
__device__ float g_chv[NROWS]; __device__ int g_chi[NROWS];
__device__ float g_clv[NROWS]; __device__ int g_cli[NROWS];
__device__ int   g_inst[2 * NI];

// ---------------- PTX helpers ----------------
__device__ __forceinline__ uint32_t smem_u32(const void* p) {
    uint32_t a;
    asm("{ .reg .u64 t; cvta.to.shared.u64 t, %1; cvt.u32.u64 %0, t; }" : "=r"(a) : "l"(p));
    return a;
}
__device__ __forceinline__ void cp16(uint32_t s, const void* g) {
    asm volatile("cp.async.cg.shared.global [%0], [%1], 16;" :: "r"(s), "l"(g));
}
__device__ __forceinline__ void ldsm4(uint32_t* r, uint32_t addr) {
    asm volatile("ldmatrix.sync.aligned.m8n8.x4.shared.b16 {%0,%1,%2,%3}, [%4];"
                 : "=r"(r[0]), "=r"(r[1]), "=r"(r[2]), "=r"(r[3]) : "r"(addr));
}
__device__ __forceinline__ void mma16816h(float* c, const uint32_t* a, const uint32_t* b) {
    asm volatile(
        "mma.sync.aligned.m16n8k16.row.col.f32.f16.f16.f32 "
        "{%0,%1,%2,%3}, {%4,%5,%6,%7}, {%8,%9}, {%0,%1,%2,%3};"
        : "+f"(c[0]), "+f"(c[1]), "+f"(c[2]), "+f"(c[3])
        : "r"(a[0]), "r"(a[1]), "r"(a[2]), "r"(a[3]), "r"(b[0]), "r"(b[1]));
}

// monotone float <-> uint key
__device__ __forceinline__ unsigned monoKey(float f) {
    unsigned u = __float_as_uint(f);
    return (u & 0x80000000u) ? ~u : (u | 0x80000000u);
}
__device__ __forceinline__ float monoDecode(unsigned k) {
    unsigned u = (k & 0x80000000u) ? (k & 0x7FFFFFFFu) : ~k;
    return __uint_as_float(u);
}

__device__ __forceinline__ uint32_t packh2(float a, float b) {
    __half2 t = __halves2half2(__float2half(a), __float2half(b));
    return *(uint32_t*)&t;
}

// ---------------- merged prep: init + Wc fp16 convert + Wcat build ----------------
__global__ void prep_kernel(const float4* __restrict__ Wc, __half2* __restrict__ wc16,
                            const float* __restrict__ Wv, const float* __restrict__ Wu,
                            const float* __restrict__ bv, const float* __restrict__ bu,
                            __half* __restrict__ wt16, float* __restrict__ bcat)
{
    int i = blockIdx.x * blockDim.x + threadIdx.x;
    if (i < 2 * NROWS) g_A[i] = 0.f;
    if (i < 16384) g_hist[i] = 0;
    if (i < 2 * L_DIM) g_bag[i] = 0.f;
    if (i < 2) { g_Z[i] = 0.f; g_maxkey[i] = 0u; }
    if (i == 0) { g_nhi = 0; g_nlo = 0; }
    if (i < (L_DIM * E_DIM) / 4) {
        float4 v = Wc[i];
        wc16[2 * i]     = __halves2half2(__float2half(v.x), __float2half(v.y));
        wc16[2 * i + 1] = __halves2half2(__float2half(v.z), __float2half(v.w));
    }
    if (i < 2 * D_DIM * L_DIM) {
        int row = i >> 9, k = i & 511;
        int j = row >> 1, e = row & 1;
        float v = e ? Wu[j * L_DIM + k] : Wv[j * L_DIM + k];
        wt16[i] = __float2half(v);
    }
    if (i < 2 * D_DIM) {
        int j = i >> 1, e = i & 1;
        bcat[i] = e ? bu[j] : bv[j];
    }
}

// ===== GEMM config (R13 shape): 128 threads, warp grid 2x2, warp tile 64x64, BK=32 =====
#define TB32 8192
#define G1_SMEM (2 * TB32 + 3 * TB32)     // conv x 2x8KB + B 3x8KB = 40KB
#define G2_SMEM (3 * 2 * TB32)            // 3 stages x (A, B) = 48KB

__global__ __launch_bounds__(128, 2)
void gemm1_fused(const float* __restrict__ X,
                 const __half* __restrict__ B16,
                 const float* __restrict__ bias,
                 __half* __restrict__ OutH)
{
    extern __shared__ __align__(1024) unsigned char dsm[];
    const int tid  = threadIdx.x;
    const int bn   = blockIdx.x;
    const int bm   = blockIdx.y;
    const int wid  = tid >> 5, lane = tid & 31;
    const int wm   = wid & 1, wn = wid >> 1;
    const int m0   = bm * 128, n0 = bn * 128;
    const int K = E_DIM, NC = E_DIM / 32;          // 32
    const uint32_t sb = smem_u32(dsm);
    const uint32_t convB = sb;
    const uint32_t bBase = sb + 2 * TB32;

    auto loadB = [&](int s, int k0) {
        uint32_t dst = bBase + s * TB32;
#pragma unroll
        for (int it = 0; it < 4; it++) {
            int q = tid + it * 128;
            int row = q >> 2;
            int c16 = q & 3;
            uint32_t off = (uint32_t)(row * 64) + (uint32_t)((c16 ^ ((row >> 1) & 3)) << 4);
            cp16(dst + off, (const char*)B16 + ((size_t)(n0 + row) * K + k0 + c16 * 8) * 2);
        }
        asm volatile("cp.async.commit_group;" ::: "memory");
    };

    // --- register-staged x conversion, row-major coalesced lanes ---
    // pass p: q = tid + p*128; row = q>>3 (0..127); c4 = q&7 (float4 within 32-float chunk)
    // one warp-LDG covers 4 full 128B row-lines -> 4 wavefronts (was 16)
    float4 xr[8];
    auto ldgX = [&](int k0) {
#pragma unroll
        for (int p = 0; p < 8; p++) {
            int q = tid + p * 128;
            int row = q >> 3, c4 = q & 7;
            xr[p] = *(const float4*)(X + (size_t)(m0 + row) * K + k0 + c4 * 4);
        }
    };
    auto stsX = [&](int buf) {
        unsigned char* hp = dsm + buf * TB32;
#pragma unroll
        for (int p = 0; p < 8; p++) {
            int q = tid + p * 128;
            int row = q >> 3, c4 = q & 7;
            uint32_t sw = (uint32_t)((row >> 1) & 3);
            uint32_t off = (uint32_t)(row * 64) +
                           ((((uint32_t)(c4 >> 1)) ^ sw) << 4) + (uint32_t)((c4 & 1) * 8);
            float4 v = xr[p];
            uint2 hv;
            hv.x = packh2(v.x, v.y);
            hv.y = packh2(v.z, v.w);
            *(uint2*)(hp + off) = hv;
        }
    };

    const int aRow = wm * 64 + (lane & 15);
    const uint32_t aK  = ((lane >> 4) & 1) * 16;
    const uint32_t aSw = (uint32_t)((aRow >> 1) & 3) << 4;
    const int bRow = wn * 64 + (lane & 7) + (((lane >> 4) & 1) << 3);
    const uint32_t bK  = ((lane >> 3) & 1) * 16;
    const uint32_t bSw = (uint32_t)((bRow >> 1) & 3) << 4;

    float acc[4][8][4];
#pragma unroll
    for (int mi = 0; mi < 4; mi++)
#pragma unroll
        for (int ni = 0; ni < 8; ni++)
#pragma unroll
            for (int e = 0; e < 4; e++) acc[mi][ni][e] = 0.f;

    loadB(0, 0);
    loadB(1, 32);
    ldgX(0);
    stsX(0);
    ldgX(32);

    for (int i = 0; i < NC; i++) {
        if (i + 1 < NC) asm volatile("cp.async.wait_group 1;" ::: "memory");
        else            asm volatile("cp.async.wait_group 0;" ::: "memory");
        __syncthreads();
        if (i + 2 < NC) loadB((i + 2) % 3, (i + 2) * 32);
        if (i + 1 < NC) stsX((i + 1) & 1);
        if (i + 2 < NC) ldgX((i + 2) * 32);

        const uint32_t sA = convB + (i & 1) * TB32;
        const uint32_t sB = bBase + (i % 3) * TB32;

#pragma unroll
        for (int ks = 0; ks < 2; ks++) {
            uint32_t aa[4][4], bb[4][4];
            const uint32_t akc = (uint32_t)(ks * 32) + aK;
            const uint32_t bkc = (uint32_t)(ks * 32) + bK;
#pragma unroll
            for (int mi = 0; mi < 4; mi++) {
                uint32_t ro = (uint32_t)((aRow + mi * 16) * 64) + (akc ^ aSw);
                ldsm4(aa[mi], sA + ro);
            }
#pragma unroll
            for (int nj = 0; nj < 4; nj++) {
                uint32_t ro = (uint32_t)((bRow + nj * 16) * 64) + (bkc ^ bSw);
                ldsm4(bb[nj], sB + ro);
            }
#pragma unroll
            for (int mi = 0; mi < 4; mi++)
#pragma unroll
                for (int nj = 0; nj < 4; nj++) {
                    mma16816h(acc[mi][2 * nj],     aa[mi], &bb[nj][0]);
                    mma16816h(acc[mi][2 * nj + 1], aa[mi], &bb[nj][2]);
                }
        }
    }

    const int rBase = m0 + wm * 64 + (lane >> 2);
    const int cBase = n0 + wn * 64 + 2 * (lane & 3);
#pragma unroll
    for (int mi = 0; mi < 4; mi++) {
#pragma unroll
        for (int ni = 0; ni < 8; ni++) {
            const int c = cBase + ni * 8;
            const float b0 = bias[c], b1 = bias[c + 1];
#pragma unroll
            for (int half = 0; half < 2; half++) {
                const int r = rBase + mi * 16 + half * 8;
                float v0 = fmaxf(acc[mi][ni][2 * half]     + b0, 0.f);
                float v1 = fmaxf(acc[mi][ni][2 * half + 1] + b1, 0.f);
                size_t o = ((size_t)r * 512 + c) >> 1;
                ((__half2*)OutH)[o] = __halves2half2(__float2half(v0), __float2half(v1));
            }
        }
    }
}

// GEMM2: A = h fp16, B = Wcat fp16, single product. Sigmoid via tanh (no expf).
__global__ __launch_bounds__(128, 2)
void gemm2_hmma(const __half* __restrict__ A16,
                const __half* __restrict__ B16,
                const float* __restrict__ bias, const float* __restrict__ Wa)
{
    extern __shared__ __align__(1024) unsigned char dsm[];
    const int tid  = threadIdx.x;
    const int bn   = blockIdx.x;
    const int bm   = blockIdx.y;
    const int wid  = tid >> 5, lane = tid & 31;
    const int wm   = wid & 1, wn = wid >> 1;
    const int m0   = bm * 128, n0 = bn * 128;
    const int K = L_DIM, NC = L_DIM / 32;   // 16
    const uint32_t sb = smem_u32(dsm);
    const int STG = 2 * TB32;

    auto loadTile = [&](uint32_t dst, const void* p, int gr0, int k0) {
#pragma unroll
        for (int it = 0; it < 4; it++) {
            int q = tid + it * 128;
            int row = q >> 2;
            int c16 = q & 3;
            uint32_t off = (uint32_t)(row * 64) + (uint32_t)((c16 ^ ((row >> 1) & 3)) << 4);
            cp16(dst + off, (const char*)p + ((size_t)(gr0 + row) * K + k0 + c16 * 8) * 2);
        }
    };
    auto loadStage = [&](int s, int k0) {
        uint32_t st = sb + s * STG;
        loadTile(st,        A16, m0, k0);
        loadTile(st + TB32, B16, n0, k0);
        asm volatile("cp.async.commit_group;" ::: "memory");
    };

    const int aRow = wm * 64 + (lane & 15);
    const uint32_t aK  = ((lane >> 4) & 1) * 16;
    const uint32_t aSw = (uint32_t)((aRow >> 1) & 3) << 4;
    const int bRow = wn * 64 + (lane & 7) + (((lane >> 4) & 1) << 3);
    const uint32_t bK  = ((lane >> 3) & 1) * 16;
    const uint32_t bSw = (uint32_t)((bRow >> 1) & 3) << 4;

    float acc[4][8][4];
#pragma unroll
    for (int mi = 0; mi < 4; mi++)
#pragma unroll
        for (int ni = 0; ni < 8; ni++)
#pragma unroll
            for (int e = 0; e < 4; e++) acc[mi][ni][e] = 0.f;

    loadStage(0, 0);
    loadStage(1, 32);

    for (int i = 0; i < NC; i++) {
        if (i + 1 < NC) asm volatile("cp.async.wait_group 1;" ::: "memory");
        else            asm volatile("cp.async.wait_group 0;" ::: "memory");
        __syncthreads();
        if (i + 2 < NC) loadStage((i + 2) % 3, (i + 2) * 32);

        const uint32_t st = sb + (i % 3) * STG;
        const uint32_t sA = st, sB = st + TB32;

#pragma unroll
        for (int ks = 0; ks < 2; ks++) {
            uint32_t aa[4][4], bb[4][4];
            const uint32_t akc = (uint32_t)(ks * 32) + aK;
            const uint32_t bkc = (uint32_t)(ks * 32) + bK;
#pragma unroll
            for (int mi = 0; mi < 4; mi++) {
                uint32_t ro = (uint32_t)((aRow + mi * 16) * 64) + (akc ^ aSw);
                ldsm4(aa[mi], sA + ro);
            }
#pragma unroll
            for (int nj = 0; nj < 4; nj++) {
                uint32_t ro = (uint32_t)((bRow + nj * 16) * 64) + (bkc ^ bSw);
                ldsm4(bb[nj], sB + ro);
            }
#pragma unroll
            for (int mi = 0; mi < 4; mi++)
#pragma unroll
                for (int nj = 0; nj < 4; nj++) {
                    mma16816h(acc[mi][2 * nj],     aa[mi], &bb[nj][0]);
                    mma16816h(acc[mi][2 * nj + 1], aa[mi], &bb[nj][2]);
                }
        }
    }

    // fused gated-attention projection epilogue (sigmoid via tanh identity)
    const int rBase = m0 + wm * 64 + (lane >> 2);
    const int cBase = n0 + wn * 64 + 2 * (lane & 3);
#pragma unroll
    for (int mi = 0; mi < 4; mi++) {
#pragma unroll
        for (int half = 0; half < 2; half++) {
            const int r = rBase + mi * 16 + half * 8;
            float s0 = 0.f, s1 = 0.f;
#pragma unroll
            for (int ni = 0; ni < 8; ni++) {
                const int c = cBase + ni * 8;
                float v0 = acc[mi][ni][2 * half]     + bias[c];
                float v1 = acc[mi][ni][2 * half + 1] + bias[c + 1];
                float gg = tanhf(v0) * (0.5f + 0.5f * tanhf(0.5f * v1));
                const int gc = c >> 1;
                s0 = fmaf(gg, Wa[gc], s0);
                s1 = fmaf(gg, Wa[D_DIM + gc], s1);
            }
            s0 += __shfl_xor_sync(0xFFFFFFFFu, s0, 1);
            s0 += __shfl_xor_sync(0xFFFFFFFFu, s0, 2);
            s1 += __shfl_xor_sync(0xFFFFFFFFu, s1, 1);
            s1 += __shfl_xor_sync(0xFFFFFFFFu, s1, 2);
            if ((lane & 3) == 0) {
                atomicAdd(&g_A[2 * r],     s0);
                atomicAdd(&g_A[2 * r + 1], s1);
            }
        }
    }
}

// ---------------- finalize: +ba, raw_attention out, per-class max, histogram ----------------
__global__ void finalize_kernel(const float* __restrict__ ba, const int* __restrict__ labelPtr,
                                float* __restrict__ out_att)
{
    __shared__ unsigned sk0, sk1;
    if (threadIdx.x == 0) { sk0 = 0u; sk1 = 0u; }
    __syncthreads();
    int i = blockIdx.x * blockDim.x + threadIdx.x;
    int lab = labelPtr ? *labelPtr : 0;
    float a0 = g_A[2 * i] + ba[0];
    float a1 = g_A[2 * i + 1] + ba[1];
    g_A[2 * i] = a0; g_A[2 * i + 1] = a1;
    out_att[i] = a0;
    out_att[NROWS + i] = a1;
    atomicMax(&sk0, monoKey(a0));
    atomicMax(&sk1, monoKey(a1));
    float sel = lab ? a1 : a0;
    atomicAdd(&g_hist[monoKey(sel) >> 18], 1);
    __syncthreads();
    if (threadIdx.x == 0) {
        atomicMax(&g_maxkey[0], sk0);
        atomicMax(&g_maxkey[1], sk1);
    }
}

// ---------------- vectorized softmax-weighted bag accumulation ----------------
__global__ void bag_kernel()
{
    const int t = threadIdx.x;
    const int sub  = t >> 6;
    const int cseg = t & 63;
    const int r0 = blockIdx.x * 256;
    const float m0 = monoDecode(g_maxkey[0]);
    const float m1 = monoDecode(g_maxkey[1]);

    float a0[8], a1[8];
#pragma unroll
    for (int j = 0; j < 8; j++) { a0[j] = 0.f; a1[j] = 0.f; }
    float z0 = 0.f, z1 = 0.f;

    for (int r = r0 + sub; r < r0 + 256; r += 4) {
        float w0 = expf(g_A[2 * r]     - m0);
        float w1 = expf(g_A[2 * r + 1] - m1);
        uint4 v = *(const uint4*)(g_h16 + (size_t)r * 512 + cseg * 8);
        const __half2* hv = (const __half2*)&v;
#pragma unroll
        for (int j = 0; j < 4; j++) {
            float lo = __low2float(hv[j]), hi = __high2float(hv[j]);
            a0[2 * j]     = fmaf(w0, lo, a0[2 * j]);
            a0[2 * j + 1] = fmaf(w0, hi, a0[2 * j + 1]);
            a1[2 * j]     = fmaf(w1, lo, a1[2 * j]);
            a1[2 * j + 1] = fmaf(w1, hi, a1[2 * j + 1]);
        }
        if (cseg == 0) { z0 += w0; z1 += w1; }
    }

    __shared__ float sm[256][17];
    __shared__ float szm[8];
#pragma unroll
    for (int j = 0; j < 8; j++) { sm[t][j] = a0[j]; sm[t][8 + j] = a1[j]; }
    if (cseg == 0) { szm[sub] = z0; szm[4 + sub] = z1; }
    __syncthreads();
    if (sub == 0) {
#pragma unroll
        for (int j = 0; j < 8; j++) {
            float s0 = sm[cseg][j] + sm[cseg + 64][j] + sm[cseg + 128][j] + sm[cseg + 192][j];
            float s1 = sm[cseg][8 + j] + sm[cseg + 64][8 + j] + sm[cseg + 128][8 + j] + sm[cseg + 192][8 + j];
            atomicAdd(&g_bag[cseg * 8 + j], s0);
            atomicAdd(&g_bag[L_DIM + cseg * 8 + j], s1);
        }
    }
    if (t == 0) {
        atomicAdd(&g_Z[0], szm[0] + szm[1] + szm[2] + szm[3]);
        atomicAdd(&g_Z[1], szm[4] + szm[5] + szm[6] + szm[7]);
    }
}

// ---------------- top-k machinery ----------------
__global__ void scan_kernel()
{
    __shared__ int csum[256];
    int t = threadIdx.x;
    int s = 0;
    for (int b = t * 64; b < t * 64 + 64; b++) s += g_hist[b];
    csum[t] = s;
    __syncthreads();
    if (t == 0) {
        int cum = 0, binhi = 0;
        for (int c = 255; c >= 0; c--) {
            if (cum + csum[c] >= NI) {
                for (int b = c * 64 + 63; b >= c * 64; b--) {
                    cum += g_hist[b];
                    if (cum >= NI) { binhi = b; break; }
                }
                break;
            }
            cum += csum[c];
        }
        g_binhi = binhi;
        cum = 0; int binlo = 16383;
        for (int c = 0; c < 256; c++) {
            if (cum + csum[c] >= NI) {
                for (int b = c * 64; b < c * 64 + 64; b++) {
                    cum += g_hist[b];
                    if (cum >= NI) { binlo = b; break; }
                }
                break;
            }
            cum += csum[c];
        }
        g_binlo = binlo;
        g_nhi = 0; g_nlo = 0;
    }
}

__global__ void cand_kernel(const int* __restrict__ labelPtr)
{
    int lab = labelPtr ? *labelPtr : 0;
    int binhi = g_binhi, binlo = g_binlo;
    for (int i = blockIdx.x * blockDim.x + threadIdx.x; i < NROWS; i += gridDim.x * blockDim.x) {
        float v = g_A[2 * i + lab];
        unsigned key = monoKey(v) >> 18;
        if ((int)key >= binhi) {
            int p = atomicAdd(&g_nhi, 1);
            g_chv[p] = v; g_chi[p] = i;
        }
        if ((int)key <= binlo) {
            int p = atomicAdd(&g_nlo, 1);
            g_clv[p] = v; g_cli[p] = i;
        }
    }
}

__global__ void select_kernel()
{
    __shared__ float sv[256];
    __shared__ int   si[256];
    __shared__ int   sp[256];
    const int t = threadIdx.x;
    const float NEG_INF = __int_as_float(0xFF800000);
    const float POS_INF = __int_as_float(0x7F800000);
    int nhi = g_nhi, nlo = g_nlo;

    for (int it = 0; it < NI; it++) {
        float bv = NEG_INF; int bi = 0x7FFFFFFF; int bp = -1;
        for (int p = t; p < nhi; p += 256) {
            float v = g_chv[p]; int idx = g_chi[p];
            if (v > bv || (v == bv && idx < bi)) { bv = v; bi = idx; bp = p; }
        }
        sv[t] = bv; si[t] = bi; sp[t] = bp;
        __syncthreads();
        for (int s = 128; s; s >>= 1) {
            if (t < s) {
                if (sv[t + s] > sv[t] || (sv[t + s] == sv[t] && si[t + s] < si[t])) {
                    sv[t] = sv[t + s]; si[t] = si[t + s]; sp[t] = sp[t + s];
                }
            }
            __syncthreads();
        }
        if (t == 0) { g_inst[it] = si[0]; g_chv[sp[0]] = NEG_INF; }
        __syncthreads();
    }
    for (int it = 0; it < NI; it++) {
        float bv = POS_INF; int bi = 0x7FFFFFFF; int bp = -1;
        for (int p = t; p < nlo; p += 256) {
            float v = g_clv[p]; int idx = g_cli[p];
            if (v < bv || (v == bv && idx < bi)) { bv = v; bi = idx; bp = p; }
        }
        sv[t] = bv; si[t] = bi; sp[t] = bp;
        __syncthreads();
        for (int s = 128; s; s >>= 1) {
            if (t < s) {
                if (sv[t + s] < sv[t] || (sv[t + s] == sv[t] && si[t + s] < si[t])) {
                    sv[t] = sv[t + s]; si[t] = si[t + s]; sp[t] = sp[t + s];
                }
            }
            __syncthreads();
        }
        if (t == 0) { g_inst[NI + it] = si[0]; g_clv[sp[0]] = POS_INF; }
        __syncthreads();
    }
}

// ---------------- instance loss (h fp16) ----------------
__global__ void loss_kernel(const int* __restrict__ labelPtr,
                            const float* __restrict__ Winst, const float* __restrict__ binst,
                            float* __restrict__ out_loss)
{
    __shared__ float sl[4];
    int lab = labelPtr ? *labelPtr : 0;
    const float* W0 = Winst + ((size_t)lab * 2 + 0) * L_DIM;
    const float* W1 = Winst + ((size_t)lab * 2 + 1) * L_DIM;
    float b0 = binst[lab * 2], b1 = binst[lab * 2 + 1];

    int warp = threadIdx.x >> 5, lane = threadIdx.x & 31;
    float lsum = 0.f;
    for (int r = warp; r < 2 * NI; r += 4) {
        const __half* hp = g_h16 + (size_t)g_inst[r] * L_DIM;
        float s0 = 0.f, s1 = 0.f;
        for (int k = lane; k < L_DIM; k += 32) {
            float v = __half2float(hp[k]);
            s0 = fmaf(v, W0[k], s0);
            s1 = fmaf(v, W1[k], s1);
        }
#pragma unroll
        for (int o = 16; o; o >>= 1) {
            s0 += __shfl_xor_sync(0xFFFFFFFFu, s0, o);
            s1 += __shfl_xor_sync(0xFFFFFFFFu, s1, o);
        }
        if (lane == 0) {
            float l0 = s0 + b0, l1 = s1 + b1;
            int tgt = (r < NI) ? 1 : 0;
            float u0 = l0 + ((tgt != 0) ? 1.f : 0.f);
            float u1 = l1 + ((tgt != 1) ? 1.f : 0.f);
            float m = fmaxf(u0, u1);
            float lse = m + logf(expf(u0 - m) + expf(u1 - m));
            float sy = (tgt == 0) ? l0 : l1;
            lsum += lse - sy;
        }
    }
    if (lane == 0) sl[warp] = lsum;
    __syncthreads();
    if (threadIdx.x == 0)
        *out_loss = (sl[0] + sl[1] + sl[2] + sl[3]) * (1.f / (2 * NI));
}

// ---------------- bag logits + softmax ----------------
__global__ void final_kernel(const float* __restrict__ Wbag, const float* __restrict__ bbag,
                             float* __restrict__ out)
{
    __shared__ float lg[2];
    int warp = threadIdx.x >> 5, lane = threadIdx.x & 31;
    if (warp < 2) {
        float s = 0.f;
        for (int k = lane; k < L_DIM; k += 32)
            s = fmaf(g_bag[warp * L_DIM + k], Wbag[warp * L_DIM + k], s);
#pragma unroll
        for (int o = 16; o; o >>= 1) s += __shfl_xor_sync(0xFFFFFFFFu, s, o);
        if (lane == 0) lg[warp] = s / g_Z[warp] + bbag[warp];
    }
    __syncthreads();
    if (threadIdx.x == 0) {
        float l0 = lg[0], l1 = lg[1];
        out[0] = l0; out[1] = l1;
        float m = fmaxf(l0, l1);
        float e0 = expf(l0 - m), e1 = expf(l1 - m);
        float s = e0 + e1;
        out[2] = e0 / s; out[3] = e1 / s;
    }
}

// ---------------- launch ----------------
extern "C" void kernel_launch(void* const* d_in, const int* in_sizes, int n_in,
                              void* d_out, int out_size)
{
    const int off = (n_in >= 14) ? 1 : 0;
    const float* x     = (const float*)d_in[0];
    const int*   label = (n_in >= 14) ? (const int*)d_in[1] : nullptr;
    const float* Wc    = (const float*)d_in[1 + off];
    const float* bc    = (const float*)d_in[2 + off];
    const float* Wv    = (const float*)d_in[3 + off];
    const float* bv    = (const float*)d_in[4 + off];
    const float* Wu    = (const float*)d_in[5 + off];
    const float* bu    = (const float*)d_in[6 + off];
    const float* Wa    = (const float*)d_in[7 + off];
    const float* ba    = (const float*)d_in[8 + off];
    const float* Winst = (const float*)d_in[9 + off];
    const float* binst = (const float*)d_in[10 + off];
    const float* Wbag  = (const float*)d_in[11 + off];
    const float* bbag  = (const float*)d_in[12 + off];
    float* out = (float*)d_out;

    void* p;
    cudaGetSymbolAddress(&p, g_h16);  __half* h16 = (__half*)p;
    cudaGetSymbolAddress(&p, g_wc16); __half* wc16 = (__half*)p;
    cudaGetSymbolAddress(&p, g_wt16); __half* wt16 = (__half*)p;
    cudaGetSymbolAddress(&p, g_bcat); float* bcat = (float*)p;

    cudaFuncSetAttribute(gemm1_fused, cudaFuncAttributeMaxDynamicSharedMemorySize, G1_SMEM);
    cudaFuncSetAttribute(gemm2_hmma,  cudaFuncAttributeMaxDynamicSharedMemorySize, G2_SMEM);

    prep_kernel<<<1024, 256>>>((const float4*)Wc, (__half2*)wc16, Wv, Wu, bv, bu, wt16, bcat);

    // GEMM1: h = relu(x @ Wc^T + bc) -> fp16 (coalesced x loads)
    gemm1_fused<<<dim3(4, NROWS / 128), 128, G1_SMEM>>>(x, wc16, bc, h16);

    // GEMM2+3 + attention fused
    gemm2_hmma<<<dim3(4, NROWS / 128), 128, G2_SMEM>>>(h16, wt16, bcat, Wa);

    finalize_kernel<<<NROWS / 256, 256>>>(ba, label, out + 4);
    scan_kernel<<<1, 256>>>();
    cand_kernel<<<NROWS / 256, 256>>>(label);
    select_kernel<<<1, 256>>>();
    loss_kernel<<<1, 128>>>(label, Winst, binst, out + 4 + 2 * NROWS);
    bag_kernel<<<512, 256>>>();
    final_kernel<<<1, 64>>>(Wbag, bbag, out);
}